// round 12
// baseline (speedup 1.0000x reference)
#include <cuda_runtime.h>
#include <cuda_bf16.h>
#include <math.h>
#include <stdint.h>

#define NVEC 12
#define CIN  8
#define COUT 8
#define DIM  64
#define VOX  (DIM*DIM*DIM)      // 262144
#define CH   (CIN*NVEC)         // 96

__device__ float g_sw[CH * 125];            // taps [c][kx*25+ky*5+kz]
__device__ float g_U[CH * 25 * 8];          // Winograd taps [c][kx*5+ky][8]
__device__ float g_fwm[CH * CH];            // mixing matrix [oc][fv]
__device__ float g_y[(size_t)2 * CH * VOX]; // conv output scratch

__device__ __forceinline__ float gelu_exact(float v) {
    return 0.5f * v * (1.0f + erff(v * 0.70710678118654752440f));
}

// ---------------------------------------------------------------------------
// Kernel W: tiny MLPs -> g_sw taps + g_fwm. MLP weights staged in smem.
// ---------------------------------------------------------------------------
__global__ __launch_bounds__(128) void weights_kernel(
    const float* __restrict__ sp, const float* __restrict__ sph,
    const float* __restrict__ bw1, const float* __restrict__ bb1,
    const float* __restrict__ bw2, const float* __restrict__ bb2,
    const float* __restrict__ bw3,
    const float* __restrict__ fw1, const float* __restrict__ fb1,
    const float* __restrict__ fw2, const float* __restrict__ fb2,
    const float* __restrict__ fw3)
{
    __shared__ float swm[872];
    int lt = threadIdx.x;
    for (int i = lt; i < 112; i += 128) swm[i] = bw1[i];
    if (lt < 8)  swm[112 + lt] = bb1[lt];
    for (int i = lt; i < 64;  i += 128) swm[120 + i] = bw2[i];
    if (lt < 8)  swm[184 + lt] = bb2[lt];
    for (int i = lt; i < 64;  i += 128) swm[192 + i] = bw3[i];
    if (lt < 24) swm[256 + lt] = fw1[lt];
    if (lt < 8)  swm[280 + lt] = fb1[lt];
    for (int i = lt; i < 64;  i += 128) swm[288 + i] = fw2[i];
    if (lt < 8)  swm[352 + lt] = fb2[lt];
    for (int i = lt; i < 512; i += 128) swm[360 + i] = fw3[i];
    __syncthreads();
    const float *s_bw1 = swm, *s_bb1 = swm+112, *s_bw2 = swm+120, *s_bb2 = swm+184,
                *s_bw3 = swm+192, *s_fw1 = swm+256, *s_fb1 = swm+280,
                *s_fw2 = swm+288, *s_fb2 = swm+352, *s_fw3 = swm+360;

    int tid = blockIdx.x * blockDim.x + threadIdx.x;
    if (tid < 1500) {
        int r = tid;
        float s0 = sp[2 * r], s1 = sp[2 * r + 1];
        float a[14];
        a[0] = s0; a[1] = s1;
        a[2] = s0 * s0; a[3] = s0 * s1; a[4] = s1 * s0; a[5] = s1 * s1;
        #pragma unroll
        for (int i = 0; i < 4; i++) { a[6 + 2*i] = a[2 + i] * s0; a[7 + 2*i] = a[2 + i] * s1; }
        float h1[8], h2[8];
        #pragma unroll
        for (int j = 0; j < 8; j++) {
            float s = s_bb1[j];
            #pragma unroll
            for (int i = 0; i < 14; i++) s += s_bw1[j * 14 + i] * a[i];
            h1[j] = gelu_exact(s);
        }
        #pragma unroll
        for (int j = 0; j < 8; j++) {
            float s = s_bb2[j];
            #pragma unroll
            for (int i = 0; i < 8; i++) s += s_bw2[j * 8 + i] * h1[i];
            h2[j] = gelu_exact(s);
        }
        int k = r / 12, v = r % 12;
        #pragma unroll
        for (int f = 0; f < 8; f++) {
            float o = 0.f;
            #pragma unroll
            for (int i = 0; i < 8; i++) o += s_bw3[f * 8 + i] * h2[i];
            g_sw[(f * 12 + v) * 125 + k] = o;
        }
    } else if (tid < 1644) {
        int r = tid - 1500;
        float c0 = sph[r];
        float a0 = c0, a1 = c0 * c0, a2 = c0 * c0 * c0;
        float h1[8], h2[8];
        #pragma unroll
        for (int j = 0; j < 8; j++) {
            float s = s_fb1[j] + s_fw1[j*3+0]*a0 + s_fw1[j*3+1]*a1 + s_fw1[j*3+2]*a2;
            h1[j] = gelu_exact(s);
        }
        #pragma unroll
        for (int j = 0; j < 8; j++) {
            float s = s_fb2[j];
            #pragma unroll
            for (int i = 0; i < 8; i++) s += s_fw2[j * 8 + i] * h1[i];
            h2[j] = gelu_exact(s);
        }
        int v = r / 12, w = r % 12;
        #pragma unroll
        for (int col = 0; col < 64; col++) {
            float o = 0.f;
            #pragma unroll
            for (int i = 0; i < 8; i++) o += s_fw3[col * 8 + i] * h2[i];
            int f = col >> 3, g = col & 7;
            g_fwm[(g * 12 + w) * CH + (f * 12 + v)] = o;
        }
    }
}

// ---------------------------------------------------------------------------
// Kernel U: Winograd F(4,5) tap transform U = G*t.
// ---------------------------------------------------------------------------
__global__ __launch_bounds__(128) void uprep_kernel()
{
    int tid = blockIdx.x * blockDim.x + threadIdx.x;
    if (tid >= CH * 25) return;
    int c = tid / 25, kxky = tid % 25;
    const float* tp = &g_sw[c * 125 + kxky * 5];
    float t0 = tp[0], t1 = tp[1], t2 = tp[2], t3 = tp[3], t4 = tp[4];
    float* up = &g_U[(c * 25 + kxky) * 8];
    up[0] = -t0;
    up[1] = (-2.f/9.f) * (t0 + t1 + t2 + t3 + t4);
    up[2] = (-2.f/9.f) * (t0 - t1 + t2 - t3 + t4);
    up[3] = (1.f/90.f) * (t0 + 2.f*t1 + 4.f*t2 + 8.f*t3 + 16.f*t4);
    up[4] = (1.f/90.f) * (t0 - 2.f*t1 + 4.f*t2 - 8.f*t3 + 16.f*t4);
    up[5] = (1.f/45.f) * (32.f*t0 + 16.f*t1 + 8.f*t2 + 4.f*t3 + 2.f*t4);
    up[6] = (1.f/45.f) * (32.f*t0 - 16.f*t1 + 8.f*t2 - 4.f*t3 + 2.f*t4);
    up[7] = t4;
}

// ---------------------------------------------------------------------------
// Kernel A: depthwise 5x5x5 conv via Winograd F(4,5) along z.
// 256 threads: warp = z-window (8), lane = (oxp, oy). Unchanged from R11.
// ---------------------------------------------------------------------------
#define CSX   0
#define CSVLO 5184
#define CSVHI 10368
#define CSU   15552
#define CONV_SMEM ((15552 + 200) * 4)

__global__ __launch_bounds__(256) void conv_kernel(const float* __restrict__ x)
{
    extern __shared__ __align__(16) float cs[];
    float* s_x   = cs + CSX;
    float* s_vlo = cs + CSVLO;
    float* s_vhi = cs + CSVHI;
    float* s_u   = cs + CSU;

    int tile = blockIdx.x;
    int c    = blockIdx.y;
    int b    = blockIdx.z;
    int tx = tile >> 4, ty = (tile >> 1) & 7, tz = tile & 1;
    int t = threadIdx.x;

    for (int i = t; i < 200; i += 256) s_u[i] = g_U[c * 200 + i];

    const float* xb = x + (size_t)(b * CH + c) * VOX;
    int gx0 = tx * 8 - 2, gy0 = ty * 8 - 2, gz0 = tz * 32 - 2;
    for (int i = t; i < 5184; i += 256) {
        int lx = i / 432, r = i % 432, ly = r / 36, lz = r % 36;
        int gx = gx0 + lx, gy = gy0 + ly, gz = gz0 + lz;
        float vv = 0.f;
        if ((unsigned)gx < 64u && (unsigned)gy < 64u && (unsigned)gz < 64u)
            vv = xb[(gx << 12) + (gy << 6) + gz];
        s_x[i] = vv;
    }
    __syncthreads();

    for (int i = t; i < 1152; i += 256) {
        int icol = i >> 3, win = i & 7;
        const float4* dp = (const float4*)&s_x[icol * 36 + win * 4];
        float4 da = dp[0], db = dp[1];
        float d0 = da.x, d1 = da.y, d2 = da.z, d3 = da.w;
        float d4 = db.x, d5 = db.y, d6 = db.z, d7 = db.w;
        float V0 = (d6 - d0) + 5.25f * (d2 - d4);
        float V7 = (d7 - d1) + 5.25f * (d3 - d5);
        float P = fmaf(-4.25f, d4, d2) + d6;
        float Q = fmaf(-4.25f, d3, d1) + d5;
        float R = fmaf(0.25f, d2, fmaf(-1.25f, d4, d6));
        float S = fmaf(0.5f, d1, fmaf(-2.5f, d3, 2.f * d5));
        float T = fmaf(4.f, d2, fmaf(-5.f, d4, d6));
        float W = fmaf(2.f, d1, fmaf(-2.5f, d3, 0.5f * d5));
        *(float4*)&s_vlo[icol * 36 + win * 4] = make_float4(V0, P + Q, P - Q, R + S);
        *(float4*)&s_vhi[icol * 36 + win * 4] = make_float4(R - S, T + W, T - W, V7);
    }
    __syncthreads();

    int w    = t >> 5;
    int lane = t & 31;
    int oxp  = lane >> 3;
    int oy   = lane & 7;
    int x0   = 2 * oxp;

    float acc0[8], acc1[8];
    #pragma unroll
    for (int i = 0; i < 8; i++) { acc0[i] = 0.f; acc1[i] = 0.f; }

    #pragma unroll
    for (int ky = 0; ky < 5; ky++) {
        float up[8], uc[8];
        #pragma unroll
        for (int d = 0; d < 6; d++) {
            if (d < 5) {
                const float4* us = (const float4*)&s_u[(d * 5 + ky) * 8];
                float4 ua = us[0], ub = us[1];
                uc[0] = ua.x; uc[1] = ua.y; uc[2] = ua.z; uc[3] = ua.w;
                uc[4] = ub.x; uc[5] = ub.y; uc[6] = ub.z; uc[7] = ub.w;
            }
            int icol = (x0 + d) * 12 + oy + ky;
            float4 vl = *(const float4*)&s_vlo[icol * 36 + w * 4];
            float4 vh = *(const float4*)&s_vhi[icol * 36 + w * 4];
            float V[8] = { vl.x, vl.y, vl.z, vl.w, vh.x, vh.y, vh.z, vh.w };
            if (d < 5) {
                #pragma unroll
                for (int i = 0; i < 8; i++) acc0[i] += uc[i] * V[i];
            }
            if (d >= 1) {
                #pragma unroll
                for (int i = 0; i < 8; i++) acc1[i] += up[i] * V[i];
            }
            if (d < 5) {
                #pragma unroll
                for (int i = 0; i < 8; i++) up[i] = uc[i];
            }
        }
    }

    size_t base = (size_t)(b * CH + c) * VOX;
    int gz = tz * 32 + w * 4;
    #pragma unroll
    for (int cc = 0; cc < 2; cc++) {
        float* m = cc ? acc1 : acc0;
        int gx = tx * 8 + x0 + cc, gy = ty * 8 + oy;
        float e1 = m[1] + m[2], f1 = m[1] - m[2];
        float e2 = m[3] + m[4], f2 = m[3] - m[4];
        float e3 = m[5] + m[6], f3 = m[5] - m[6];
        float y0 = m[0] + e1 + e2 + e3;
        float y1 = fmaf(2.f, f2, f1) + 0.5f * f3;
        float y2 = fmaf(4.f, e2, e1) + 0.25f * e3;
        float y3 = fmaf(8.f, f2, f1) + fmaf(0.125f, f3, m[7]);
        *(float4*)&g_y[base + (gx << 12) + (gy << 6) + gz] =
            make_float4(y0, y1, y2, y3);
    }
}

// ---------------------------------------------------------------------------
// Kernel B: per-voxel 96x96 mixing, mma.sync bf16 hi/lo 3-pass, fp32 accum.
// 256 threads: 8 warps x one 16-row m-tile -> 16 warps/SM (2x concurrency).
// ---------------------------------------------------------------------------
#define PA32 52
#define PB32 52
#define PD   132
#define OFF_AH 0
#define OFF_AL 26624
#define OFF_BH 53248
#define OFF_BL 73216
#define OFF_SB 93184
#define MIX_SMEM_TOTAL (93184 + 512)
#define MIX_TILES 4

__device__ __forceinline__ void mma16816(float* c, const uint32_t a[4],
                                         uint32_t b0, uint32_t b1) {
    asm volatile(
        "mma.sync.aligned.m16n8k16.row.col.f32.bf16.bf16.f32 "
        "{%0,%1,%2,%3}, {%4,%5,%6,%7}, {%8,%9}, {%0,%1,%2,%3};"
        : "+f"(c[0]), "+f"(c[1]), "+f"(c[2]), "+f"(c[3])
        : "r"(a[0]), "r"(a[1]), "r"(a[2]), "r"(a[3]), "r"(b0), "r"(b1));
}

__device__ __forceinline__ void split2(float y0, float y1, uint32_t& hi, uint32_t& lo) {
    uint32_t u0 = __float_as_uint(y0), u1 = __float_as_uint(y1);
    float h0 = __uint_as_float(u0 & 0xFFFF0000u);
    float h1 = __uint_as_float(u1 & 0xFFFF0000u);
    hi = __byte_perm(u0, u1, 0x7632);
    asm("cvt.rn.bf16x2.f32 %0, %1, %2;" : "=r"(lo) : "f"(y1 - h1), "f"(y0 - h0));
}

__global__ __launch_bounds__(256) void mix_kernel(
    const float* __restrict__ bias, float* __restrict__ out)
{
    extern __shared__ __align__(16) char smem[];
    uint32_t* Ah = (uint32_t*)(smem + OFF_AH);
    uint32_t* Al = (uint32_t*)(smem + OFF_AL);
    uint32_t* Bh = (uint32_t*)(smem + OFF_BH);
    uint32_t* Bl = (uint32_t*)(smem + OFF_BL);
    float*    s_b = (float*)(smem + OFF_SB);

    int t    = threadIdx.x;
    int wid  = t >> 5;
    int lane = t & 31;
    int g    = lane >> 2;
    int q    = lane & 3;

    for (int idx = t; idx < CH * 48; idx += 256) {
        int oc = idx / 48, j = idx % 48;
        uint32_t hi, lo;
        split2(g_fwm[oc * CH + 2 * j], g_fwm[oc * CH + 2 * j + 1], hi, lo);
        Bh[oc * PB32 + j] = hi;
        Bl[oc * PB32 + j] = lo;
    }
    if (t < CH) s_b[t] = bias[t / 12];

    int row = t >> 1;
    int cpb = (t & 1) * 24;
    int sw  = (row >> 3) & 3;
    int sw0 = (2 * wid) & 3, sw1 = (2 * wid + 1) & 3;
    int m0  = wid * 16;

    for (int it = 0; it < MIX_TILES; it++) {
        int tv = blockIdx.x * MIX_TILES + it;
        int b  = tv >> 11;
        int p0 = (tv & 2047) * 128;

        const float* yb = g_y + (size_t)b * CH * VOX + p0 + row;
        #pragma unroll 8
        for (int cp = cpb; cp < cpb + 24; cp++) {
            uint32_t hi, lo;
            split2(yb[(size_t)(2 * cp) * VOX], yb[(size_t)(2 * cp + 1) * VOX], hi, lo);
            Ah[row * PA32 + (cp ^ sw)] = hi;
            Al[row * PA32 + (cp ^ sw)] = lo;
        }
        __syncthreads();

        float acc[12][4];
        #pragma unroll
        for (int n = 0; n < 12; n++)
            #pragma unroll
            for (int i = 0; i < 4; i++) acc[n][i] = 0.f;

        const uint32_t* Asrc[3] = { Ah, Al, Ah };
        const uint32_t* Bsrc[3] = { Bh, Bh, Bl };
        #pragma unroll 1
        for (int pass = 0; pass < 3; pass++) {
            const uint32_t* As = Asrc[pass];
            const uint32_t* Bs = Bsrc[pass];
            #pragma unroll
            for (int k = 0; k < 6; k++) {
                int c0 = 8 * k + q;
                uint32_t af[4];
                int row0 = m0 + g;
                af[0] = As[row0 * PA32       + (c0 ^ sw0)];
                af[1] = As[(row0 + 8) * PA32 + (c0 ^ sw1)];
                af[2] = As[row0 * PA32       + ((c0 + 4) ^ sw0)];
                af[3] = As[(row0 + 8) * PA32 + ((c0 + 4) ^ sw1)];
                #pragma unroll
                for (int n = 0; n < 12; n++) {
                    const uint32_t* pb = Bs + (n * 8 + g) * PB32 + 8 * k + q;
                    mma16816(acc[n], af, pb[0], pb[4]);
                }
            }
        }

        __syncthreads();
        float* D = (float*)(smem + OFF_AH);
        int r1 = m0 + g;
        #pragma unroll
        for (int n = 0; n < 12; n++) {
            int ocb = n * 8 + 2 * q;
            D[(ocb)     * PD + r1]     = acc[n][0];
            D[(ocb + 1) * PD + r1]     = acc[n][1];
            D[(ocb)     * PD + r1 + 8] = acc[n][2];
            D[(ocb + 1) * PD + r1 + 8] = acc[n][3];
        }
        __syncthreads();

        float* ob = out + (size_t)b * CH * VOX + p0;
        for (int i = t; i < CH * 128; i += 256) {
            int cch = i >> 7, p = i & 127;
            ob[(size_t)cch * VOX + p] = D[cch * PD + p] + s_b[cch];
        }
        __syncthreads();
    }
}

// ---------------------------------------------------------------------------
extern "C" void kernel_launch(void* const* d_in, const int* in_sizes, int n_in,
                              void* d_out, int out_size)
{
    const float* x    = (const float*)d_in[0];
    const float* sp   = (const float*)d_in[1];
    const float* sph  = (const float*)d_in[2];
    const float* bw1  = (const float*)d_in[3];
    const float* bb1  = (const float*)d_in[4];
    const float* bw2  = (const float*)d_in[5];
    const float* bb2  = (const float*)d_in[6];
    const float* bw3  = (const float*)d_in[7];
    const float* fw1  = (const float*)d_in[8];
    const float* fb1  = (const float*)d_in[9];
    const float* fw2  = (const float*)d_in[10];
    const float* fb2  = (const float*)d_in[11];
    const float* fw3  = (const float*)d_in[12];
    const float* bias = (const float*)d_in[13];

    cudaFuncSetAttribute(conv_kernel, cudaFuncAttributeMaxDynamicSharedMemorySize,
                         CONV_SMEM);
    cudaFuncSetAttribute(mix_kernel, cudaFuncAttributeMaxDynamicSharedMemorySize,
                         MIX_SMEM_TOTAL);

    weights_kernel<<<13, 128>>>(sp, sph, bw1, bb1, bw2, bb2, bw3,
                                fw1, fb1, fw2, fb2, fw3);
    uprep_kernel<<<19, 128>>>();

    dim3 gA(128, CH, 2);
    conv_kernel<<<gA, 256, CONV_SMEM>>>(x);

    mix_kernel<<<4096 / MIX_TILES, 256, MIX_SMEM_TOTAL>>>(bias, (float*)d_out);
}

// round 13
// speedup vs baseline: 1.0367x; 1.0367x over previous
#include <cuda_runtime.h>
#include <cuda_bf16.h>
#include <math.h>
#include <stdint.h>

#define NVEC 12
#define CIN  8
#define COUT 8
#define DIM  64
#define VOX  (DIM*DIM*DIM)      // 262144
#define CH   (CIN*NVEC)         // 96

__device__ float g_sw[CH * 125];            // taps [c][kx*25+ky*5+kz]
__device__ float g_U[CH * 25 * 8];          // Winograd taps [c][kx*5+ky][8]
__device__ float g_fwm[CH * CH];            // mixing matrix [oc][fv]
__device__ float g_y[(size_t)2 * CH * VOX]; // conv output scratch

__device__ __forceinline__ float gelu_exact(float v) {
    return 0.5f * v * (1.0f + erff(v * 0.70710678118654752440f));
}

// ---------------------------------------------------------------------------
// Kernel W: tiny MLPs -> g_sw taps + g_fwm. MLP weights staged in smem.
// ---------------------------------------------------------------------------
__global__ __launch_bounds__(128) void weights_kernel(
    const float* __restrict__ sp, const float* __restrict__ sph,
    const float* __restrict__ bw1, const float* __restrict__ bb1,
    const float* __restrict__ bw2, const float* __restrict__ bb2,
    const float* __restrict__ bw3,
    const float* __restrict__ fw1, const float* __restrict__ fb1,
    const float* __restrict__ fw2, const float* __restrict__ fb2,
    const float* __restrict__ fw3)
{
    __shared__ float swm[872];
    int lt = threadIdx.x;
    for (int i = lt; i < 112; i += 128) swm[i] = bw1[i];
    if (lt < 8)  swm[112 + lt] = bb1[lt];
    for (int i = lt; i < 64;  i += 128) swm[120 + i] = bw2[i];
    if (lt < 8)  swm[184 + lt] = bb2[lt];
    for (int i = lt; i < 64;  i += 128) swm[192 + i] = bw3[i];
    if (lt < 24) swm[256 + lt] = fw1[lt];
    if (lt < 8)  swm[280 + lt] = fb1[lt];
    for (int i = lt; i < 64;  i += 128) swm[288 + i] = fw2[i];
    if (lt < 8)  swm[352 + lt] = fb2[lt];
    for (int i = lt; i < 512; i += 128) swm[360 + i] = fw3[i];
    __syncthreads();
    const float *s_bw1 = swm, *s_bb1 = swm+112, *s_bw2 = swm+120, *s_bb2 = swm+184,
                *s_bw3 = swm+192, *s_fw1 = swm+256, *s_fb1 = swm+280,
                *s_fw2 = swm+288, *s_fb2 = swm+352, *s_fw3 = swm+360;

    int tid = blockIdx.x * blockDim.x + threadIdx.x;
    if (tid < 1500) {
        int r = tid;
        float s0 = sp[2 * r], s1 = sp[2 * r + 1];
        float a[14];
        a[0] = s0; a[1] = s1;
        a[2] = s0 * s0; a[3] = s0 * s1; a[4] = s1 * s0; a[5] = s1 * s1;
        #pragma unroll
        for (int i = 0; i < 4; i++) { a[6 + 2*i] = a[2 + i] * s0; a[7 + 2*i] = a[2 + i] * s1; }
        float h1[8], h2[8];
        #pragma unroll
        for (int j = 0; j < 8; j++) {
            float s = s_bb1[j];
            #pragma unroll
            for (int i = 0; i < 14; i++) s += s_bw1[j * 14 + i] * a[i];
            h1[j] = gelu_exact(s);
        }
        #pragma unroll
        for (int j = 0; j < 8; j++) {
            float s = s_bb2[j];
            #pragma unroll
            for (int i = 0; i < 8; i++) s += s_bw2[j * 8 + i] * h1[i];
            h2[j] = gelu_exact(s);
        }
        int k = r / 12, v = r % 12;
        #pragma unroll
        for (int f = 0; f < 8; f++) {
            float o = 0.f;
            #pragma unroll
            for (int i = 0; i < 8; i++) o += s_bw3[f * 8 + i] * h2[i];
            g_sw[(f * 12 + v) * 125 + k] = o;
        }
    } else if (tid < 1644) {
        int r = tid - 1500;
        float c0 = sph[r];
        float a0 = c0, a1 = c0 * c0, a2 = c0 * c0 * c0;
        float h1[8], h2[8];
        #pragma unroll
        for (int j = 0; j < 8; j++) {
            float s = s_fb1[j] + s_fw1[j*3+0]*a0 + s_fw1[j*3+1]*a1 + s_fw1[j*3+2]*a2;
            h1[j] = gelu_exact(s);
        }
        #pragma unroll
        for (int j = 0; j < 8; j++) {
            float s = s_fb2[j];
            #pragma unroll
            for (int i = 0; i < 8; i++) s += s_fw2[j * 8 + i] * h1[i];
            h2[j] = gelu_exact(s);
        }
        int v = r / 12, w = r % 12;
        #pragma unroll
        for (int col = 0; col < 64; col++) {
            float o = 0.f;
            #pragma unroll
            for (int i = 0; i < 8; i++) o += s_fw3[col * 8 + i] * h2[i];
            int f = col >> 3, g = col & 7;
            g_fwm[(g * 12 + w) * CH + (f * 12 + v)] = o;
        }
    }
}

// ---------------------------------------------------------------------------
// Kernel U: Winograd F(4,5) tap transform U = G*t.
// ---------------------------------------------------------------------------
__global__ __launch_bounds__(128) void uprep_kernel()
{
    int tid = blockIdx.x * blockDim.x + threadIdx.x;
    if (tid >= CH * 25) return;
    int c = tid / 25, kxky = tid % 25;
    const float* tp = &g_sw[c * 125 + kxky * 5];
    float t0 = tp[0], t1 = tp[1], t2 = tp[2], t3 = tp[3], t4 = tp[4];
    float* up = &g_U[(c * 25 + kxky) * 8];
    up[0] = -t0;
    up[1] = (-2.f/9.f) * (t0 + t1 + t2 + t3 + t4);
    up[2] = (-2.f/9.f) * (t0 - t1 + t2 - t3 + t4);
    up[3] = (1.f/90.f) * (t0 + 2.f*t1 + 4.f*t2 + 8.f*t3 + 16.f*t4);
    up[4] = (1.f/90.f) * (t0 - 2.f*t1 + 4.f*t2 - 8.f*t3 + 16.f*t4);
    up[5] = (1.f/45.f) * (32.f*t0 + 16.f*t1 + 8.f*t2 + 4.f*t3 + 2.f*t4);
    up[6] = (1.f/45.f) * (32.f*t0 - 16.f*t1 + 8.f*t2 - 4.f*t3 + 2.f*t4);
    up[7] = t4;
}

// ---------------------------------------------------------------------------
// Kernel A: depthwise 5x5x5 conv via Winograd F(4,5) along z.
// 256 threads: warp = z-window (8), lane = (oxp, oy). Unchanged from R11.
// ---------------------------------------------------------------------------
#define CSX   0
#define CSVLO 5184
#define CSVHI 10368
#define CSU   15552
#define CONV_SMEM ((15552 + 200) * 4)

__global__ __launch_bounds__(256) void conv_kernel(const float* __restrict__ x)
{
    extern __shared__ __align__(16) float cs[];
    float* s_x   = cs + CSX;
    float* s_vlo = cs + CSVLO;
    float* s_vhi = cs + CSVHI;
    float* s_u   = cs + CSU;

    int tile = blockIdx.x;
    int c    = blockIdx.y;
    int b    = blockIdx.z;
    int tx = tile >> 4, ty = (tile >> 1) & 7, tz = tile & 1;
    int t = threadIdx.x;

    for (int i = t; i < 200; i += 256) s_u[i] = g_U[c * 200 + i];

    const float* xb = x + (size_t)(b * CH + c) * VOX;
    int gx0 = tx * 8 - 2, gy0 = ty * 8 - 2, gz0 = tz * 32 - 2;
    for (int i = t; i < 5184; i += 256) {
        int lx = i / 432, r = i % 432, ly = r / 36, lz = r % 36;
        int gx = gx0 + lx, gy = gy0 + ly, gz = gz0 + lz;
        float vv = 0.f;
        if ((unsigned)gx < 64u && (unsigned)gy < 64u && (unsigned)gz < 64u)
            vv = xb[(gx << 12) + (gy << 6) + gz];
        s_x[i] = vv;
    }
    __syncthreads();

    for (int i = t; i < 1152; i += 256) {
        int icol = i >> 3, win = i & 7;
        const float4* dp = (const float4*)&s_x[icol * 36 + win * 4];
        float4 da = dp[0], db = dp[1];
        float d0 = da.x, d1 = da.y, d2 = da.z, d3 = da.w;
        float d4 = db.x, d5 = db.y, d6 = db.z, d7 = db.w;
        float V0 = (d6 - d0) + 5.25f * (d2 - d4);
        float V7 = (d7 - d1) + 5.25f * (d3 - d5);
        float P = fmaf(-4.25f, d4, d2) + d6;
        float Q = fmaf(-4.25f, d3, d1) + d5;
        float R = fmaf(0.25f, d2, fmaf(-1.25f, d4, d6));
        float S = fmaf(0.5f, d1, fmaf(-2.5f, d3, 2.f * d5));
        float T = fmaf(4.f, d2, fmaf(-5.f, d4, d6));
        float W = fmaf(2.f, d1, fmaf(-2.5f, d3, 0.5f * d5));
        *(float4*)&s_vlo[icol * 36 + win * 4] = make_float4(V0, P + Q, P - Q, R + S);
        *(float4*)&s_vhi[icol * 36 + win * 4] = make_float4(R - S, T + W, T - W, V7);
    }
    __syncthreads();

    int w    = t >> 5;
    int lane = t & 31;
    int oxp  = lane >> 3;
    int oy   = lane & 7;
    int x0   = 2 * oxp;

    float acc0[8], acc1[8];
    #pragma unroll
    for (int i = 0; i < 8; i++) { acc0[i] = 0.f; acc1[i] = 0.f; }

    #pragma unroll
    for (int ky = 0; ky < 5; ky++) {
        float up[8], uc[8];
        #pragma unroll
        for (int d = 0; d < 6; d++) {
            if (d < 5) {
                const float4* us = (const float4*)&s_u[(d * 5 + ky) * 8];
                float4 ua = us[0], ub = us[1];
                uc[0] = ua.x; uc[1] = ua.y; uc[2] = ua.z; uc[3] = ua.w;
                uc[4] = ub.x; uc[5] = ub.y; uc[6] = ub.z; uc[7] = ub.w;
            }
            int icol = (x0 + d) * 12 + oy + ky;
            float4 vl = *(const float4*)&s_vlo[icol * 36 + w * 4];
            float4 vh = *(const float4*)&s_vhi[icol * 36 + w * 4];
            float V[8] = { vl.x, vl.y, vl.z, vl.w, vh.x, vh.y, vh.z, vh.w };
            if (d < 5) {
                #pragma unroll
                for (int i = 0; i < 8; i++) acc0[i] += uc[i] * V[i];
            }
            if (d >= 1) {
                #pragma unroll
                for (int i = 0; i < 8; i++) acc1[i] += up[i] * V[i];
            }
            if (d < 5) {
                #pragma unroll
                for (int i = 0; i < 8; i++) up[i] = uc[i];
            }
        }
    }

    size_t base = (size_t)(b * CH + c) * VOX;
    int gz = tz * 32 + w * 4;
    #pragma unroll
    for (int cc = 0; cc < 2; cc++) {
        float* m = cc ? acc1 : acc0;
        int gx = tx * 8 + x0 + cc, gy = ty * 8 + oy;
        float e1 = m[1] + m[2], f1 = m[1] - m[2];
        float e2 = m[3] + m[4], f2 = m[3] - m[4];
        float e3 = m[5] + m[6], f3 = m[5] - m[6];
        float y0 = m[0] + e1 + e2 + e3;
        float y1 = fmaf(2.f, f2, f1) + 0.5f * f3;
        float y2 = fmaf(4.f, e2, e1) + 0.25f * e3;
        float y3 = fmaf(8.f, f2, f1) + fmaf(0.125f, f3, m[7]);
        *(float4*)&g_y[base + (gx << 12) + (gy << 6) + gz] =
            make_float4(y0, y1, y2, y3);
    }
}

// ---------------------------------------------------------------------------
// Kernel B: per-voxel 96x96 mixing, mma.sync bf16, fp32 accum.
// R6 structure (128 threads, 4 warps x 2 m-tiles) with FUSED hi/lo passes:
// fragments (Ah,Al,Bh,Bl) loaded ONCE per k-step, 6 MMAs issued per (k,n).
// LDS count per tile: 576 -> 384.
// ---------------------------------------------------------------------------
#define PA32 52
#define PB32 52
#define PD   132
#define OFF_AH 0
#define OFF_AL 26624
#define OFF_BH 53248
#define OFF_BL 73216
#define MIX_SMEM_TOTAL 93184
#define MIX_TILES 4

__device__ __forceinline__ void mma16816(float* c, const uint32_t a[4],
                                         uint32_t b0, uint32_t b1) {
    asm volatile(
        "mma.sync.aligned.m16n8k16.row.col.f32.bf16.bf16.f32 "
        "{%0,%1,%2,%3}, {%4,%5,%6,%7}, {%8,%9}, {%0,%1,%2,%3};"
        : "+f"(c[0]), "+f"(c[1]), "+f"(c[2]), "+f"(c[3])
        : "r"(a[0]), "r"(a[1]), "r"(a[2]), "r"(a[3]), "r"(b0), "r"(b1));
}

__device__ __forceinline__ void split2(float y0, float y1, uint32_t& hi, uint32_t& lo) {
    uint32_t u0 = __float_as_uint(y0), u1 = __float_as_uint(y1);
    float h0 = __uint_as_float(u0 & 0xFFFF0000u);
    float h1 = __uint_as_float(u1 & 0xFFFF0000u);
    hi = __byte_perm(u0, u1, 0x7632);
    asm("cvt.rn.bf16x2.f32 %0, %1, %2;" : "=r"(lo) : "f"(y1 - h1), "f"(y0 - h0));
}

__global__ __launch_bounds__(128) void mix_kernel(
    const float* __restrict__ bias, float* __restrict__ out)
{
    extern __shared__ __align__(16) char smem[];
    uint32_t* Ah = (uint32_t*)(smem + OFF_AH);
    uint32_t* Al = (uint32_t*)(smem + OFF_AL);
    uint32_t* Bh = (uint32_t*)(smem + OFF_BH);
    uint32_t* Bl = (uint32_t*)(smem + OFF_BL);

    int t    = threadIdx.x;
    int wid  = t >> 5;
    int lane = t & 31;
    int g    = lane >> 2;
    int q    = lane & 3;

    for (int idx = t; idx < CH * 48; idx += 128) {
        int oc = idx / 48, j = idx % 48;
        uint32_t hi, lo;
        split2(g_fwm[oc * CH + 2 * j], g_fwm[oc * CH + 2 * j + 1], hi, lo);
        Bh[oc * PB32 + j] = hi;
        Bl[oc * PB32 + j] = lo;
    }
    float bv[8];
    #pragma unroll
    for (int i = 0; i < 8; i++) bv[i] = bias[i];

    for (int it = 0; it < MIX_TILES; it++) {
        int tv = blockIdx.x * MIX_TILES + it;
        int b  = tv >> 11;
        int p0 = (tv & 2047) * 128;

        {
            const float* yb = g_y + (size_t)b * CH * VOX + p0 + t;
            int sw = (t >> 3) & 3;
            #pragma unroll 8
            for (int cp = 0; cp < 48; cp++) {
                uint32_t hi, lo;
                split2(yb[(size_t)(2 * cp) * VOX], yb[(size_t)(2 * cp + 1) * VOX], hi, lo);
                Ah[t * PA32 + (cp ^ sw)] = hi;
                Al[t * PA32 + (cp ^ sw)] = lo;
            }
        }
        __syncthreads();

        int m0 = wid * 32;
        float acc[2][12][4];
        #pragma unroll
        for (int mt = 0; mt < 2; mt++)
            #pragma unroll
            for (int n = 0; n < 12; n++)
                #pragma unroll
                for (int i = 0; i < 4; i++) acc[mt][n][i] = 0.f;

        // Fused hi/lo mainloop: load all fragments once per k-step,
        // issue Ah*Bh + Al*Bh + Ah*Bl (lo*lo dropped, same as 3-pass).
        #pragma unroll
        for (int k = 0; k < 6; k++) {
            int c0 = 8 * k + q;
            uint32_t afh[2][4], afl[2][4];
            #pragma unroll
            for (int mt = 0; mt < 2; mt++) {
                int row0 = m0 + mt * 16 + g;
                int s0 = 2 * mt, s1 = 2 * mt + 1;
                int i00 = row0 * PA32       + (c0 ^ s0);
                int i01 = (row0 + 8) * PA32 + (c0 ^ s1);
                int i10 = row0 * PA32       + ((c0 + 4) ^ s0);
                int i11 = (row0 + 8) * PA32 + ((c0 + 4) ^ s1);
                afh[mt][0] = Ah[i00]; afh[mt][1] = Ah[i01];
                afh[mt][2] = Ah[i10]; afh[mt][3] = Ah[i11];
                afl[mt][0] = Al[i00]; afl[mt][1] = Al[i01];
                afl[mt][2] = Al[i10]; afl[mt][3] = Al[i11];
            }
            #pragma unroll
            for (int n = 0; n < 12; n++) {
                const uint32_t* pbh = Bh + (n * 8 + g) * PB32 + 8 * k + q;
                const uint32_t* pbl = Bl + (n * 8 + g) * PB32 + 8 * k + q;
                uint32_t b0h = pbh[0], b1h = pbh[4];
                uint32_t b0l = pbl[0], b1l = pbl[4];
                mma16816(acc[0][n], afh[0], b0h, b1h);
                mma16816(acc[1][n], afh[1], b0h, b1h);
                mma16816(acc[0][n], afl[0], b0h, b1h);
                mma16816(acc[1][n], afl[1], b0h, b1h);
                mma16816(acc[0][n], afh[0], b0l, b1l);
                mma16816(acc[1][n], afh[1], b0l, b1l);
            }
        }

        __syncthreads();
        float* D = (float*)(smem + OFF_AH);
        #pragma unroll
        for (int mt = 0; mt < 2; mt++) {
            int r1 = m0 + mt * 16 + g;
            #pragma unroll
            for (int n = 0; n < 12; n++) {
                int ocb = n * 8 + 2 * q;
                D[(ocb)     * PD + r1]     = acc[mt][n][0];
                D[(ocb + 1) * PD + r1]     = acc[mt][n][1];
                D[(ocb)     * PD + r1 + 8] = acc[mt][n][2];
                D[(ocb + 1) * PD + r1 + 8] = acc[mt][n][3];
            }
        }
        __syncthreads();

        float* ob = out + (size_t)b * CH * VOX + p0 + t;
        #pragma unroll
        for (int c = 0; c < CH; c++)
            ob[(size_t)c * VOX] = D[c * PD + t] + bv[c / 12];
        __syncthreads();
    }
}

// ---------------------------------------------------------------------------
extern "C" void kernel_launch(void* const* d_in, const int* in_sizes, int n_in,
                              void* d_out, int out_size)
{
    const float* x    = (const float*)d_in[0];
    const float* sp   = (const float*)d_in[1];
    const float* sph  = (const float*)d_in[2];
    const float* bw1  = (const float*)d_in[3];
    const float* bb1  = (const float*)d_in[4];
    const float* bw2  = (const float*)d_in[5];
    const float* bb2  = (const float*)d_in[6];
    const float* bw3  = (const float*)d_in[7];
    const float* fw1  = (const float*)d_in[8];
    const float* fb1  = (const float*)d_in[9];
    const float* fw2  = (const float*)d_in[10];
    const float* fb2  = (const float*)d_in[11];
    const float* fw3  = (const float*)d_in[12];
    const float* bias = (const float*)d_in[13];

    cudaFuncSetAttribute(conv_kernel, cudaFuncAttributeMaxDynamicSharedMemorySize,
                         CONV_SMEM);
    cudaFuncSetAttribute(mix_kernel, cudaFuncAttributeMaxDynamicSharedMemorySize,
                         MIX_SMEM_TOTAL);

    weights_kernel<<<13, 128>>>(sp, sph, bw1, bb1, bw2, bb2, bw3,
                                fw1, fb1, fw2, fb2, fw3);
    uprep_kernel<<<19, 128>>>();

    dim3 gA(128, CH, 2);
    conv_kernel<<<gA, 256, CONV_SMEM>>>(x);

    mix_kernel<<<4096 / MIX_TILES, 128, MIX_SMEM_TOTAL>>>(bias, (float*)d_out);
}

// round 14
// speedup vs baseline: 1.0402x; 1.0034x over previous
#include <cuda_runtime.h>
#include <cuda_bf16.h>
#include <math.h>
#include <stdint.h>

#define NVEC 12
#define CIN  8
#define COUT 8
#define DIM  64
#define VOX  (DIM*DIM*DIM)      // 262144
#define CH   (CIN*NVEC)         // 96

__device__ float g_sw[CH * 125];            // taps [c][kx*25+ky*5+kz]
__device__ float g_U[CH * 25 * 8];          // Winograd taps [c][kx*5+ky][8]
__device__ float g_fwm[CH * CH];            // mixing matrix [oc][fv]
__device__ float g_y[(size_t)2 * CH * VOX]; // conv output scratch

__device__ __forceinline__ float gelu_exact(float v) {
    return 0.5f * v * (1.0f + erff(v * 0.70710678118654752440f));
}

// ---------------------------------------------------------------------------
// Kernel W: tiny MLPs -> g_sw taps + g_fwm. MLP weights staged in smem.
// ---------------------------------------------------------------------------
__global__ __launch_bounds__(128) void weights_kernel(
    const float* __restrict__ sp, const float* __restrict__ sph,
    const float* __restrict__ bw1, const float* __restrict__ bb1,
    const float* __restrict__ bw2, const float* __restrict__ bb2,
    const float* __restrict__ bw3,
    const float* __restrict__ fw1, const float* __restrict__ fb1,
    const float* __restrict__ fw2, const float* __restrict__ fb2,
    const float* __restrict__ fw3)
{
    __shared__ float swm[872];
    int lt = threadIdx.x;
    for (int i = lt; i < 112; i += 128) swm[i] = bw1[i];
    if (lt < 8)  swm[112 + lt] = bb1[lt];
    for (int i = lt; i < 64;  i += 128) swm[120 + i] = bw2[i];
    if (lt < 8)  swm[184 + lt] = bb2[lt];
    for (int i = lt; i < 64;  i += 128) swm[192 + i] = bw3[i];
    if (lt < 24) swm[256 + lt] = fw1[lt];
    if (lt < 8)  swm[280 + lt] = fb1[lt];
    for (int i = lt; i < 64;  i += 128) swm[288 + i] = fw2[i];
    if (lt < 8)  swm[352 + lt] = fb2[lt];
    for (int i = lt; i < 512; i += 128) swm[360 + i] = fw3[i];
    __syncthreads();
    const float *s_bw1 = swm, *s_bb1 = swm+112, *s_bw2 = swm+120, *s_bb2 = swm+184,
                *s_bw3 = swm+192, *s_fw1 = swm+256, *s_fb1 = swm+280,
                *s_fw2 = swm+288, *s_fb2 = swm+352, *s_fw3 = swm+360;

    int tid = blockIdx.x * blockDim.x + threadIdx.x;
    if (tid < 1500) {
        int r = tid;
        float s0 = sp[2 * r], s1 = sp[2 * r + 1];
        float a[14];
        a[0] = s0; a[1] = s1;
        a[2] = s0 * s0; a[3] = s0 * s1; a[4] = s1 * s0; a[5] = s1 * s1;
        #pragma unroll
        for (int i = 0; i < 4; i++) { a[6 + 2*i] = a[2 + i] * s0; a[7 + 2*i] = a[2 + i] * s1; }
        float h1[8], h2[8];
        #pragma unroll
        for (int j = 0; j < 8; j++) {
            float s = s_bb1[j];
            #pragma unroll
            for (int i = 0; i < 14; i++) s += s_bw1[j * 14 + i] * a[i];
            h1[j] = gelu_exact(s);
        }
        #pragma unroll
        for (int j = 0; j < 8; j++) {
            float s = s_bb2[j];
            #pragma unroll
            for (int i = 0; i < 8; i++) s += s_bw2[j * 8 + i] * h1[i];
            h2[j] = gelu_exact(s);
        }
        int k = r / 12, v = r % 12;
        #pragma unroll
        for (int f = 0; f < 8; f++) {
            float o = 0.f;
            #pragma unroll
            for (int i = 0; i < 8; i++) o += s_bw3[f * 8 + i] * h2[i];
            g_sw[(f * 12 + v) * 125 + k] = o;
        }
    } else if (tid < 1644) {
        int r = tid - 1500;
        float c0 = sph[r];
        float a0 = c0, a1 = c0 * c0, a2 = c0 * c0 * c0;
        float h1[8], h2[8];
        #pragma unroll
        for (int j = 0; j < 8; j++) {
            float s = s_fb1[j] + s_fw1[j*3+0]*a0 + s_fw1[j*3+1]*a1 + s_fw1[j*3+2]*a2;
            h1[j] = gelu_exact(s);
        }
        #pragma unroll
        for (int j = 0; j < 8; j++) {
            float s = s_fb2[j];
            #pragma unroll
            for (int i = 0; i < 8; i++) s += s_fw2[j * 8 + i] * h1[i];
            h2[j] = gelu_exact(s);
        }
        int v = r / 12, w = r % 12;
        #pragma unroll
        for (int col = 0; col < 64; col++) {
            float o = 0.f;
            #pragma unroll
            for (int i = 0; i < 8; i++) o += s_fw3[col * 8 + i] * h2[i];
            int f = col >> 3, g = col & 7;
            g_fwm[(g * 12 + w) * CH + (f * 12 + v)] = o;
        }
    }
}

// ---------------------------------------------------------------------------
// Kernel U: Winograd F(4,5) tap transform U = G*t.
// ---------------------------------------------------------------------------
__global__ __launch_bounds__(128) void uprep_kernel()
{
    int tid = blockIdx.x * blockDim.x + threadIdx.x;
    if (tid >= CH * 25) return;
    int c = tid / 25, kxky = tid % 25;
    const float* tp = &g_sw[c * 125 + kxky * 5];
    float t0 = tp[0], t1 = tp[1], t2 = tp[2], t3 = tp[3], t4 = tp[4];
    float* up = &g_U[(c * 25 + kxky) * 8];
    up[0] = -t0;
    up[1] = (-2.f/9.f) * (t0 + t1 + t2 + t3 + t4);
    up[2] = (-2.f/9.f) * (t0 - t1 + t2 - t3 + t4);
    up[3] = (1.f/90.f) * (t0 + 2.f*t1 + 4.f*t2 + 8.f*t3 + 16.f*t4);
    up[4] = (1.f/90.f) * (t0 - 2.f*t1 + 4.f*t2 - 8.f*t3 + 16.f*t4);
    up[5] = (1.f/45.f) * (32.f*t0 + 16.f*t1 + 8.f*t2 + 4.f*t3 + 2.f*t4);
    up[6] = (1.f/45.f) * (32.f*t0 - 16.f*t1 + 8.f*t2 - 4.f*t3 + 2.f*t4);
    up[7] = t4;
}

// ---------------------------------------------------------------------------
// Kernel A: depthwise 5x5x5 conv via Winograd F(4,5) along z.
// 256 threads. Phase-2 index decomposition fixed: win=i/144, icol=i%144
// -> lanes walk consecutive icols (quad-stride 9, gcd(9,32)=1) ->
// conflict-free LDS/STS (was 4-way conflicted with icol=i>>3).
// ---------------------------------------------------------------------------
#define CSX   0
#define CSVLO 5184
#define CSVHI 10368
#define CSU   15552
#define CONV_SMEM ((15552 + 200) * 4)

__global__ __launch_bounds__(256) void conv_kernel(const float* __restrict__ x)
{
    extern __shared__ __align__(16) float cs[];
    float* s_x   = cs + CSX;
    float* s_vlo = cs + CSVLO;
    float* s_vhi = cs + CSVHI;
    float* s_u   = cs + CSU;

    int tile = blockIdx.x;
    int c    = blockIdx.y;
    int b    = blockIdx.z;
    int tx = tile >> 4, ty = (tile >> 1) & 7, tz = tile & 1;
    int t = threadIdx.x;

    for (int i = t; i < 200; i += 256) s_u[i] = g_U[c * 200 + i];

    const float* xb = x + (size_t)(b * CH + c) * VOX;
    int gx0 = tx * 8 - 2, gy0 = ty * 8 - 2, gz0 = tz * 32 - 2;
    for (int i = t; i < 5184; i += 256) {
        int lx = i / 432, r = i % 432, ly = r / 36, lz = r % 36;
        int gx = gx0 + lx, gy = gy0 + ly, gz = gz0 + lz;
        float vv = 0.f;
        if ((unsigned)gx < 64u && (unsigned)gy < 64u && (unsigned)gz < 64u)
            vv = xb[(gx << 12) + (gy << 6) + gz];
        s_x[i] = vv;
    }
    __syncthreads();

    // phase 2: conflict-free decomposition (win outer, icol inner)
    for (int i = t; i < 1152; i += 256) {
        int win  = i / 144;
        int icol = i - win * 144;
        const float4* dp = (const float4*)&s_x[icol * 36 + win * 4];
        float4 da = dp[0], db = dp[1];
        float d0 = da.x, d1 = da.y, d2 = da.z, d3 = da.w;
        float d4 = db.x, d5 = db.y, d6 = db.z, d7 = db.w;
        float V0 = (d6 - d0) + 5.25f * (d2 - d4);
        float V7 = (d7 - d1) + 5.25f * (d3 - d5);
        float P = fmaf(-4.25f, d4, d2) + d6;
        float Q = fmaf(-4.25f, d3, d1) + d5;
        float R = fmaf(0.25f, d2, fmaf(-1.25f, d4, d6));
        float S = fmaf(0.5f, d1, fmaf(-2.5f, d3, 2.f * d5));
        float T = fmaf(4.f, d2, fmaf(-5.f, d4, d6));
        float W = fmaf(2.f, d1, fmaf(-2.5f, d3, 0.5f * d5));
        *(float4*)&s_vlo[icol * 36 + win * 4] = make_float4(V0, P + Q, P - Q, R + S);
        *(float4*)&s_vhi[icol * 36 + win * 4] = make_float4(R - S, T + W, T - W, V7);
    }
    __syncthreads();

    int w    = t >> 5;
    int lane = t & 31;
    int oxp  = lane >> 3;
    int oy   = lane & 7;
    int x0   = 2 * oxp;

    float acc0[8], acc1[8];
    #pragma unroll
    for (int i = 0; i < 8; i++) { acc0[i] = 0.f; acc1[i] = 0.f; }

    #pragma unroll
    for (int ky = 0; ky < 5; ky++) {
        float up[8], uc[8];
        #pragma unroll
        for (int d = 0; d < 6; d++) {
            if (d < 5) {
                const float4* us = (const float4*)&s_u[(d * 5 + ky) * 8];
                float4 ua = us[0], ub = us[1];
                uc[0] = ua.x; uc[1] = ua.y; uc[2] = ua.z; uc[3] = ua.w;
                uc[4] = ub.x; uc[5] = ub.y; uc[6] = ub.z; uc[7] = ub.w;
            }
            int icol = (x0 + d) * 12 + oy + ky;
            float4 vl = *(const float4*)&s_vlo[icol * 36 + w * 4];
            float4 vh = *(const float4*)&s_vhi[icol * 36 + w * 4];
            float V[8] = { vl.x, vl.y, vl.z, vl.w, vh.x, vh.y, vh.z, vh.w };
            if (d < 5) {
                #pragma unroll
                for (int i = 0; i < 8; i++) acc0[i] += uc[i] * V[i];
            }
            if (d >= 1) {
                #pragma unroll
                for (int i = 0; i < 8; i++) acc1[i] += up[i] * V[i];
            }
            if (d < 5) {
                #pragma unroll
                for (int i = 0; i < 8; i++) up[i] = uc[i];
            }
        }
    }

    size_t base = (size_t)(b * CH + c) * VOX;
    int gz = tz * 32 + w * 4;
    #pragma unroll
    for (int cc = 0; cc < 2; cc++) {
        float* m = cc ? acc1 : acc0;
        int gx = tx * 8 + x0 + cc, gy = ty * 8 + oy;
        float e1 = m[1] + m[2], f1 = m[1] - m[2];
        float e2 = m[3] + m[4], f2 = m[3] - m[4];
        float e3 = m[5] + m[6], f3 = m[5] - m[6];
        float y0 = m[0] + e1 + e2 + e3;
        float y1 = fmaf(2.f, f2, f1) + 0.5f * f3;
        float y2 = fmaf(4.f, e2, e1) + 0.25f * e3;
        float y3 = fmaf(8.f, f2, f1) + fmaf(0.125f, f3, m[7]);
        *(float4*)&g_y[base + (gx << 12) + (gy << 6) + gz] =
            make_float4(y0, y1, y2, y3);
    }
}

// ---------------------------------------------------------------------------
// Kernel B: per-voxel 96x96 mixing — R13 fused-pass version (known good).
// ---------------------------------------------------------------------------
#define PA32 52
#define PB32 52
#define PD   132
#define OFF_AH 0
#define OFF_AL 26624
#define OFF_BH 53248
#define OFF_BL 73216
#define MIX_SMEM_TOTAL 93184
#define MIX_TILES 4

__device__ __forceinline__ void mma16816(float* c, const uint32_t a[4],
                                         uint32_t b0, uint32_t b1) {
    asm volatile(
        "mma.sync.aligned.m16n8k16.row.col.f32.bf16.bf16.f32 "
        "{%0,%1,%2,%3}, {%4,%5,%6,%7}, {%8,%9}, {%0,%1,%2,%3};"
        : "+f"(c[0]), "+f"(c[1]), "+f"(c[2]), "+f"(c[3])
        : "r"(a[0]), "r"(a[1]), "r"(a[2]), "r"(a[3]), "r"(b0), "r"(b1));
}

__device__ __forceinline__ void split2(float y0, float y1, uint32_t& hi, uint32_t& lo) {
    uint32_t u0 = __float_as_uint(y0), u1 = __float_as_uint(y1);
    float h0 = __uint_as_float(u0 & 0xFFFF0000u);
    float h1 = __uint_as_float(u1 & 0xFFFF0000u);
    hi = __byte_perm(u0, u1, 0x7632);
    asm("cvt.rn.bf16x2.f32 %0, %1, %2;" : "=r"(lo) : "f"(y1 - h1), "f"(y0 - h0));
}

__global__ __launch_bounds__(128) void mix_kernel(
    const float* __restrict__ bias, float* __restrict__ out)
{
    extern __shared__ __align__(16) char smem[];
    uint32_t* Ah = (uint32_t*)(smem + OFF_AH);
    uint32_t* Al = (uint32_t*)(smem + OFF_AL);
    uint32_t* Bh = (uint32_t*)(smem + OFF_BH);
    uint32_t* Bl = (uint32_t*)(smem + OFF_BL);

    int t    = threadIdx.x;
    int wid  = t >> 5;
    int lane = t & 31;
    int g    = lane >> 2;
    int q    = lane & 3;

    for (int idx = t; idx < CH * 48; idx += 128) {
        int oc = idx / 48, j = idx % 48;
        uint32_t hi, lo;
        split2(g_fwm[oc * CH + 2 * j], g_fwm[oc * CH + 2 * j + 1], hi, lo);
        Bh[oc * PB32 + j] = hi;
        Bl[oc * PB32 + j] = lo;
    }
    float bv[8];
    #pragma unroll
    for (int i = 0; i < 8; i++) bv[i] = bias[i];

    for (int it = 0; it < MIX_TILES; it++) {
        int tv = blockIdx.x * MIX_TILES + it;
        int b  = tv >> 11;
        int p0 = (tv & 2047) * 128;

        {
            const float* yb = g_y + (size_t)b * CH * VOX + p0 + t;
            int sw = (t >> 3) & 3;
            #pragma unroll 8
            for (int cp = 0; cp < 48; cp++) {
                uint32_t hi, lo;
                split2(yb[(size_t)(2 * cp) * VOX], yb[(size_t)(2 * cp + 1) * VOX], hi, lo);
                Ah[t * PA32 + (cp ^ sw)] = hi;
                Al[t * PA32 + (cp ^ sw)] = lo;
            }
        }
        __syncthreads();

        int m0 = wid * 32;
        float acc[2][12][4];
        #pragma unroll
        for (int mt = 0; mt < 2; mt++)
            #pragma unroll
            for (int n = 0; n < 12; n++)
                #pragma unroll
                for (int i = 0; i < 4; i++) acc[mt][n][i] = 0.f;

        #pragma unroll
        for (int k = 0; k < 6; k++) {
            int c0 = 8 * k + q;
            uint32_t afh[2][4], afl[2][4];
            #pragma unroll
            for (int mt = 0; mt < 2; mt++) {
                int row0 = m0 + mt * 16 + g;
                int s0 = 2 * mt, s1 = 2 * mt + 1;
                int i00 = row0 * PA32       + (c0 ^ s0);
                int i01 = (row0 + 8) * PA32 + (c0 ^ s1);
                int i10 = row0 * PA32       + ((c0 + 4) ^ s0);
                int i11 = (row0 + 8) * PA32 + ((c0 + 4) ^ s1);
                afh[mt][0] = Ah[i00]; afh[mt][1] = Ah[i01];
                afh[mt][2] = Ah[i10]; afh[mt][3] = Ah[i11];
                afl[mt][0] = Al[i00]; afl[mt][1] = Al[i01];
                afl[mt][2] = Al[i10]; afl[mt][3] = Al[i11];
            }
            #pragma unroll
            for (int n = 0; n < 12; n++) {
                const uint32_t* pbh = Bh + (n * 8 + g) * PB32 + 8 * k + q;
                const uint32_t* pbl = Bl + (n * 8 + g) * PB32 + 8 * k + q;
                uint32_t b0h = pbh[0], b1h = pbh[4];
                uint32_t b0l = pbl[0], b1l = pbl[4];
                mma16816(acc[0][n], afh[0], b0h, b1h);
                mma16816(acc[1][n], afh[1], b0h, b1h);
                mma16816(acc[0][n], afl[0], b0h, b1h);
                mma16816(acc[1][n], afl[1], b0h, b1h);
                mma16816(acc[0][n], afh[0], b0l, b1l);
                mma16816(acc[1][n], afh[1], b0l, b1l);
            }
        }

        __syncthreads();
        float* D = (float*)(smem + OFF_AH);
        #pragma unroll
        for (int mt = 0; mt < 2; mt++) {
            int r1 = m0 + mt * 16 + g;
            #pragma unroll
            for (int n = 0; n < 12; n++) {
                int ocb = n * 8 + 2 * q;
                D[(ocb)     * PD + r1]     = acc[mt][n][0];
                D[(ocb + 1) * PD + r1]     = acc[mt][n][1];
                D[(ocb)     * PD + r1 + 8] = acc[mt][n][2];
                D[(ocb + 1) * PD + r1 + 8] = acc[mt][n][3];
            }
        }
        __syncthreads();

        float* ob = out + (size_t)b * CH * VOX + p0 + t;
        #pragma unroll
        for (int c = 0; c < CH; c++)
            ob[(size_t)c * VOX] = D[c * PD + t] + bv[c / 12];
        __syncthreads();
    }
}

// ---------------------------------------------------------------------------
extern "C" void kernel_launch(void* const* d_in, const int* in_sizes, int n_in,
                              void* d_out, int out_size)
{
    const float* x    = (const float*)d_in[0];
    const float* sp   = (const float*)d_in[1];
    const float* sph  = (const float*)d_in[2];
    const float* bw1  = (const float*)d_in[3];
    const float* bb1  = (const float*)d_in[4];
    const float* bw2  = (const float*)d_in[5];
    const float* bb2  = (const float*)d_in[6];
    const float* bw3  = (const float*)d_in[7];
    const float* fw1  = (const float*)d_in[8];
    const float* fb1  = (const float*)d_in[9];
    const float* fw2  = (const float*)d_in[10];
    const float* fb2  = (const float*)d_in[11];
    const float* fw3  = (const float*)d_in[12];
    const float* bias = (const float*)d_in[13];

    cudaFuncSetAttribute(conv_kernel, cudaFuncAttributeMaxDynamicSharedMemorySize,
                         CONV_SMEM);
    cudaFuncSetAttribute(mix_kernel, cudaFuncAttributeMaxDynamicSharedMemorySize,
                         MIX_SMEM_TOTAL);

    weights_kernel<<<13, 128>>>(sp, sph, bw1, bb1, bw2, bb2, bw3,
                                fw1, fb1, fw2, fb2, fw3);
    uprep_kernel<<<19, 128>>>();

    dim3 gA(128, CH, 2);
    conv_kernel<<<gA, 256, CONV_SMEM>>>(x);

    mix_kernel<<<4096 / MIX_TILES, 128, MIX_SMEM_TOTAL>>>(bias, (float*)d_out);
}

// round 15
// speedup vs baseline: 1.0579x; 1.0171x over previous
#include <cuda_runtime.h>
#include <cuda_bf16.h>
#include <math.h>
#include <stdint.h>

#define NVEC 12
#define CIN  8
#define COUT 8
#define DIM  64
#define VOX  (DIM*DIM*DIM)      // 262144
#define CH   (CIN*NVEC)         // 96

__device__ float g_sw[CH * 125];            // taps [c][kx*25+ky*5+kz]
__device__ float g_U[CH * 25 * 8];          // Winograd taps [c][kx*5+ky][8]
__device__ float g_fwm[CH * CH];            // mixing matrix [oc][fv]
__device__ float g_y[(size_t)2 * CH * VOX]; // conv output scratch

__device__ __forceinline__ float gelu_exact(float v) {
    return 0.5f * v * (1.0f + erff(v * 0.70710678118654752440f));
}

// ---------------------------------------------------------------------------
// Kernel W: tiny MLPs -> g_sw taps + g_fwm. MLP weights staged in smem.
// ---------------------------------------------------------------------------
__global__ __launch_bounds__(128) void weights_kernel(
    const float* __restrict__ sp, const float* __restrict__ sph,
    const float* __restrict__ bw1, const float* __restrict__ bb1,
    const float* __restrict__ bw2, const float* __restrict__ bb2,
    const float* __restrict__ bw3,
    const float* __restrict__ fw1, const float* __restrict__ fb1,
    const float* __restrict__ fw2, const float* __restrict__ fb2,
    const float* __restrict__ fw3)
{
    __shared__ float swm[872];
    int lt = threadIdx.x;
    for (int i = lt; i < 112; i += 128) swm[i] = bw1[i];
    if (lt < 8)  swm[112 + lt] = bb1[lt];
    for (int i = lt; i < 64;  i += 128) swm[120 + i] = bw2[i];
    if (lt < 8)  swm[184 + lt] = bb2[lt];
    for (int i = lt; i < 64;  i += 128) swm[192 + i] = bw3[i];
    if (lt < 24) swm[256 + lt] = fw1[lt];
    if (lt < 8)  swm[280 + lt] = fb1[lt];
    for (int i = lt; i < 64;  i += 128) swm[288 + i] = fw2[i];
    if (lt < 8)  swm[352 + lt] = fb2[lt];
    for (int i = lt; i < 512; i += 128) swm[360 + i] = fw3[i];
    __syncthreads();
    const float *s_bw1 = swm, *s_bb1 = swm+112, *s_bw2 = swm+120, *s_bb2 = swm+184,
                *s_bw3 = swm+192, *s_fw1 = swm+256, *s_fb1 = swm+280,
                *s_fw2 = swm+288, *s_fb2 = swm+352, *s_fw3 = swm+360;

    int tid = blockIdx.x * blockDim.x + threadIdx.x;
    if (tid < 1500) {
        int r = tid;
        float s0 = sp[2 * r], s1 = sp[2 * r + 1];
        float a[14];
        a[0] = s0; a[1] = s1;
        a[2] = s0 * s0; a[3] = s0 * s1; a[4] = s1 * s0; a[5] = s1 * s1;
        #pragma unroll
        for (int i = 0; i < 4; i++) { a[6 + 2*i] = a[2 + i] * s0; a[7 + 2*i] = a[2 + i] * s1; }
        float h1[8], h2[8];
        #pragma unroll
        for (int j = 0; j < 8; j++) {
            float s = s_bb1[j];
            #pragma unroll
            for (int i = 0; i < 14; i++) s += s_bw1[j * 14 + i] * a[i];
            h1[j] = gelu_exact(s);
        }
        #pragma unroll
        for (int j = 0; j < 8; j++) {
            float s = s_bb2[j];
            #pragma unroll
            for (int i = 0; i < 8; i++) s += s_bw2[j * 8 + i] * h1[i];
            h2[j] = gelu_exact(s);
        }
        int k = r / 12, v = r % 12;
        #pragma unroll
        for (int f = 0; f < 8; f++) {
            float o = 0.f;
            #pragma unroll
            for (int i = 0; i < 8; i++) o += s_bw3[f * 8 + i] * h2[i];
            g_sw[(f * 12 + v) * 125 + k] = o;
        }
    } else if (tid < 1644) {
        int r = tid - 1500;
        float c0 = sph[r];
        float a0 = c0, a1 = c0 * c0, a2 = c0 * c0 * c0;
        float h1[8], h2[8];
        #pragma unroll
        for (int j = 0; j < 8; j++) {
            float s = s_fb1[j] + s_fw1[j*3+0]*a0 + s_fw1[j*3+1]*a1 + s_fw1[j*3+2]*a2;
            h1[j] = gelu_exact(s);
        }
        #pragma unroll
        for (int j = 0; j < 8; j++) {
            float s = s_fb2[j];
            #pragma unroll
            for (int i = 0; i < 8; i++) s += s_fw2[j * 8 + i] * h1[i];
            h2[j] = gelu_exact(s);
        }
        int v = r / 12, w = r % 12;
        #pragma unroll
        for (int col = 0; col < 64; col++) {
            float o = 0.f;
            #pragma unroll
            for (int i = 0; i < 8; i++) o += s_fw3[col * 8 + i] * h2[i];
            int f = col >> 3, g = col & 7;
            g_fwm[(g * 12 + w) * CH + (f * 12 + v)] = o;
        }
    }
}

// ---------------------------------------------------------------------------
// Kernel U: Winograd F(4,5) tap transform U = G*t.
// ---------------------------------------------------------------------------
__global__ __launch_bounds__(128) void uprep_kernel()
{
    int tid = blockIdx.x * blockDim.x + threadIdx.x;
    if (tid >= CH * 25) return;
    int c = tid / 25, kxky = tid % 25;
    const float* tp = &g_sw[c * 125 + kxky * 5];
    float t0 = tp[0], t1 = tp[1], t2 = tp[2], t3 = tp[3], t4 = tp[4];
    float* up = &g_U[(c * 25 + kxky) * 8];
    up[0] = -t0;
    up[1] = (-2.f/9.f) * (t0 + t1 + t2 + t3 + t4);
    up[2] = (-2.f/9.f) * (t0 - t1 + t2 - t3 + t4);
    up[3] = (1.f/90.f) * (t0 + 2.f*t1 + 4.f*t2 + 8.f*t3 + 16.f*t4);
    up[4] = (1.f/90.f) * (t0 - 2.f*t1 + 4.f*t2 - 8.f*t3 + 16.f*t4);
    up[5] = (1.f/45.f) * (32.f*t0 + 16.f*t1 + 8.f*t2 + 4.f*t3 + 2.f*t4);
    up[6] = (1.f/45.f) * (32.f*t0 - 16.f*t1 + 8.f*t2 - 4.f*t3 + 2.f*t4);
    up[7] = t4;
}

// ---------------------------------------------------------------------------
// Kernel A: depthwise 5x5x5 conv via Winograd F(4,5) along z.
// Tile 16x8x32, 256 threads, 4 x-columns per thread (V-reuse 10 FMA/LDS.128).
// Lane map: xq=t>>6, oy=(t>>3)&7, w=t&7 -> V quad diff = 9*doy + dw != 0
// within warp -> conflict-free.
// ---------------------------------------------------------------------------
#define CSX   0
#define CSVLO 8640                 // s_x = 20*12*36
#define CSVHI 17280                // + 240*36
#define CSU   25920                // + 240*36
#define CONV_SMEM ((25920 + 200) * 4)

__global__ __launch_bounds__(256, 2) void conv_kernel(const float* __restrict__ x)
{
    extern __shared__ __align__(16) float cs[];
    float* s_x   = cs + CSX;     // 20 x 12 x 36
    float* s_vlo = cs + CSVLO;   // 240 icols x 36
    float* s_vhi = cs + CSVHI;
    float* s_u   = cs + CSU;     // 200

    int tile = blockIdx.x;            // 0..63
    int c    = blockIdx.y;            // 0..95
    int b    = blockIdx.z;
    int tx = tile >> 4, ty = (tile >> 1) & 7, tz = tile & 1;   // tx 0..3
    int t = threadIdx.x;

    for (int i = t; i < 200; i += 256) s_u[i] = g_U[c * 200 + i];

    // ---- phase 1: halo 20 x 12 x 36 ----
    const float* xb = x + (size_t)(b * CH + c) * VOX;
    int gx0 = tx * 16 - 2, gy0 = ty * 8 - 2, gz0 = tz * 32 - 2;
    for (int i = t; i < 8640; i += 256) {
        int lx = i / 432, r = i % 432, ly = r / 36, lz = r % 36;
        int gx = gx0 + lx, gy = gy0 + ly, gz = gz0 + lz;
        float vv = 0.f;
        if ((unsigned)gx < 64u && (unsigned)gy < 64u && (unsigned)gz < 64u)
            vv = xb[(gx << 12) + (gy << 6) + gz];
        s_x[i] = vv;
    }
    __syncthreads();

    // ---- phase 2: V = BT*d, 240 cols x 8 windows ----
    for (int i = t; i < 1920; i += 256) {
        int win  = i / 240;
        int icol = i - win * 240;
        const float4* dp = (const float4*)&s_x[icol * 36 + win * 4];
        float4 da = dp[0], db = dp[1];
        float d0 = da.x, d1 = da.y, d2 = da.z, d3 = da.w;
        float d4 = db.x, d5 = db.y, d6 = db.z, d7 = db.w;
        float V0 = (d6 - d0) + 5.25f * (d2 - d4);
        float V7 = (d7 - d1) + 5.25f * (d3 - d5);
        float P = fmaf(-4.25f, d4, d2) + d6;
        float Q = fmaf(-4.25f, d3, d1) + d5;
        float R = fmaf(0.25f, d2, fmaf(-1.25f, d4, d6));
        float S = fmaf(0.5f, d1, fmaf(-2.5f, d3, 2.f * d5));
        float T = fmaf(4.f, d2, fmaf(-5.f, d4, d6));
        float W = fmaf(2.f, d1, fmaf(-2.5f, d3, 0.5f * d5));
        *(float4*)&s_vlo[icol * 36 + win * 4] = make_float4(V0, P + Q, P - Q, R + S);
        *(float4*)&s_vhi[icol * 36 + win * 4] = make_float4(R - S, T + W, T - W, V7);
    }
    __syncthreads();

    // ---- phase 3: 4 x-columns per thread ----
    int xq = t >> 6;           // 0..3
    int oy = (t >> 3) & 7;
    int w  = t & 7;            // z-window
    int x0 = 4 * xq;

    float acc[4][8];
    #pragma unroll
    for (int cc = 0; cc < 4; cc++)
        #pragma unroll
        for (int i = 0; i < 8; i++) acc[cc][i] = 0.f;

    #pragma unroll
    for (int ky = 0; ky < 5; ky++) {
        float U[5][8];
        #pragma unroll
        for (int j = 0; j < 5; j++) {
            const float4* us = (const float4*)&s_u[(j * 5 + ky) * 8];
            float4 ua = us[0], ub = us[1];
            U[j][0] = ua.x; U[j][1] = ua.y; U[j][2] = ua.z; U[j][3] = ua.w;
            U[j][4] = ub.x; U[j][5] = ub.y; U[j][6] = ub.z; U[j][7] = ub.w;
        }
        #pragma unroll
        for (int d = 0; d < 8; d++) {
            int icol = (x0 + d) * 12 + oy + ky;
            float4 vl = *(const float4*)&s_vlo[icol * 36 + w * 4];
            float4 vh = *(const float4*)&s_vhi[icol * 36 + w * 4];
            float V[8] = { vl.x, vl.y, vl.z, vl.w, vh.x, vh.y, vh.z, vh.w };
            #pragma unroll
            for (int cc = 0; cc < 4; cc++) {
                int j = d - cc;
                if (j >= 0 && j <= 4) {
                    #pragma unroll
                    for (int i = 0; i < 8; i++) acc[cc][i] += U[j][i] * V[i];
                }
            }
        }
    }

    size_t base = (size_t)(b * CH + c) * VOX;
    int gz = tz * 32 + w * 4;
    int gy = ty * 8 + oy;
    #pragma unroll
    for (int cc = 0; cc < 4; cc++) {
        float* m = acc[cc];
        int gx = tx * 16 + x0 + cc;
        float e1 = m[1] + m[2], f1 = m[1] - m[2];
        float e2 = m[3] + m[4], f2 = m[3] - m[4];
        float e3 = m[5] + m[6], f3 = m[5] - m[6];
        float y0 = m[0] + e1 + e2 + e3;
        float y1 = fmaf(2.f, f2, f1) + 0.5f * f3;
        float y2 = fmaf(4.f, e2, e1) + 0.25f * e3;
        float y3 = fmaf(8.f, f2, f1) + fmaf(0.125f, f3, m[7]);
        *(float4*)&g_y[base + (gx << 12) + (gy << 6) + gz] =
            make_float4(y0, y1, y2, y3);
    }
}

// ---------------------------------------------------------------------------
// Kernel B: per-voxel 96x96 mixing — R13 fused-pass version (known good).
// ---------------------------------------------------------------------------
#define PA32 52
#define PB32 52
#define PD   132
#define OFF_AH 0
#define OFF_AL 26624
#define OFF_BH 53248
#define OFF_BL 73216
#define MIX_SMEM_TOTAL 93184
#define MIX_TILES 4

__device__ __forceinline__ void mma16816(float* c, const uint32_t a[4],
                                         uint32_t b0, uint32_t b1) {
    asm volatile(
        "mma.sync.aligned.m16n8k16.row.col.f32.bf16.bf16.f32 "
        "{%0,%1,%2,%3}, {%4,%5,%6,%7}, {%8,%9}, {%0,%1,%2,%3};"
        : "+f"(c[0]), "+f"(c[1]), "+f"(c[2]), "+f"(c[3])
        : "r"(a[0]), "r"(a[1]), "r"(a[2]), "r"(a[3]), "r"(b0), "r"(b1));
}

__device__ __forceinline__ void split2(float y0, float y1, uint32_t& hi, uint32_t& lo) {
    uint32_t u0 = __float_as_uint(y0), u1 = __float_as_uint(y1);
    float h0 = __uint_as_float(u0 & 0xFFFF0000u);
    float h1 = __uint_as_float(u1 & 0xFFFF0000u);
    hi = __byte_perm(u0, u1, 0x7632);
    asm("cvt.rn.bf16x2.f32 %0, %1, %2;" : "=r"(lo) : "f"(y1 - h1), "f"(y0 - h0));
}

__global__ __launch_bounds__(128) void mix_kernel(
    const float* __restrict__ bias, float* __restrict__ out)
{
    extern __shared__ __align__(16) char smem[];
    uint32_t* Ah = (uint32_t*)(smem + OFF_AH);
    uint32_t* Al = (uint32_t*)(smem + OFF_AL);
    uint32_t* Bh = (uint32_t*)(smem + OFF_BH);
    uint32_t* Bl = (uint32_t*)(smem + OFF_BL);

    int t    = threadIdx.x;
    int wid  = t >> 5;
    int lane = t & 31;
    int g    = lane >> 2;
    int q    = lane & 3;

    for (int idx = t; idx < CH * 48; idx += 128) {
        int oc = idx / 48, j = idx % 48;
        uint32_t hi, lo;
        split2(g_fwm[oc * CH + 2 * j], g_fwm[oc * CH + 2 * j + 1], hi, lo);
        Bh[oc * PB32 + j] = hi;
        Bl[oc * PB32 + j] = lo;
    }
    float bv[8];
    #pragma unroll
    for (int i = 0; i < 8; i++) bv[i] = bias[i];

    for (int it = 0; it < MIX_TILES; it++) {
        int tv = blockIdx.x * MIX_TILES + it;
        int b  = tv >> 11;
        int p0 = (tv & 2047) * 128;

        {
            const float* yb = g_y + (size_t)b * CH * VOX + p0 + t;
            int sw = (t >> 3) & 3;
            #pragma unroll 8
            for (int cp = 0; cp < 48; cp++) {
                uint32_t hi, lo;
                split2(yb[(size_t)(2 * cp) * VOX], yb[(size_t)(2 * cp + 1) * VOX], hi, lo);
                Ah[t * PA32 + (cp ^ sw)] = hi;
                Al[t * PA32 + (cp ^ sw)] = lo;
            }
        }
        __syncthreads();

        int m0 = wid * 32;
        float acc[2][12][4];
        #pragma unroll
        for (int mt = 0; mt < 2; mt++)
            #pragma unroll
            for (int n = 0; n < 12; n++)
                #pragma unroll
                for (int i = 0; i < 4; i++) acc[mt][n][i] = 0.f;

        #pragma unroll
        for (int k = 0; k < 6; k++) {
            int c0 = 8 * k + q;
            uint32_t afh[2][4], afl[2][4];
            #pragma unroll
            for (int mt = 0; mt < 2; mt++) {
                int row0 = m0 + mt * 16 + g;
                int s0 = 2 * mt, s1 = 2 * mt + 1;
                int i00 = row0 * PA32       + (c0 ^ s0);
                int i01 = (row0 + 8) * PA32 + (c0 ^ s1);
                int i10 = row0 * PA32       + ((c0 + 4) ^ s0);
                int i11 = (row0 + 8) * PA32 + ((c0 + 4) ^ s1);
                afh[mt][0] = Ah[i00]; afh[mt][1] = Ah[i01];
                afh[mt][2] = Ah[i10]; afh[mt][3] = Ah[i11];
                afl[mt][0] = Al[i00]; afl[mt][1] = Al[i01];
                afl[mt][2] = Al[i10]; afl[mt][3] = Al[i11];
            }
            #pragma unroll
            for (int n = 0; n < 12; n++) {
                const uint32_t* pbh = Bh + (n * 8 + g) * PB32 + 8 * k + q;
                const uint32_t* pbl = Bl + (n * 8 + g) * PB32 + 8 * k + q;
                uint32_t b0h = pbh[0], b1h = pbh[4];
                uint32_t b0l = pbl[0], b1l = pbl[4];
                mma16816(acc[0][n], afh[0], b0h, b1h);
                mma16816(acc[1][n], afh[1], b0h, b1h);
                mma16816(acc[0][n], afl[0], b0h, b1h);
                mma16816(acc[1][n], afl[1], b0h, b1h);
                mma16816(acc[0][n], afh[0], b0l, b1l);
                mma16816(acc[1][n], afh[1], b0l, b1l);
            }
        }

        __syncthreads();
        float* D = (float*)(smem + OFF_AH);
        #pragma unroll
        for (int mt = 0; mt < 2; mt++) {
            int r1 = m0 + mt * 16 + g;
            #pragma unroll
            for (int n = 0; n < 12; n++) {
                int ocb = n * 8 + 2 * q;
                D[(ocb)     * PD + r1]     = acc[mt][n][0];
                D[(ocb + 1) * PD + r1]     = acc[mt][n][1];
                D[(ocb)     * PD + r1 + 8] = acc[mt][n][2];
                D[(ocb + 1) * PD + r1 + 8] = acc[mt][n][3];
            }
        }
        __syncthreads();

        float* ob = out + (size_t)b * CH * VOX + p0 + t;
        #pragma unroll
        for (int c = 0; c < CH; c++)
            ob[(size_t)c * VOX] = D[c * PD + t] + bv[c / 12];
        __syncthreads();
    }
}

// ---------------------------------------------------------------------------
extern "C" void kernel_launch(void* const* d_in, const int* in_sizes, int n_in,
                              void* d_out, int out_size)
{
    const float* x    = (const float*)d_in[0];
    const float* sp   = (const float*)d_in[1];
    const float* sph  = (const float*)d_in[2];
    const float* bw1  = (const float*)d_in[3];
    const float* bb1  = (const float*)d_in[4];
    const float* bw2  = (const float*)d_in[5];
    const float* bb2  = (const float*)d_in[6];
    const float* bw3  = (const float*)d_in[7];
    const float* fw1  = (const float*)d_in[8];
    const float* fb1  = (const float*)d_in[9];
    const float* fw2  = (const float*)d_in[10];
    const float* fb2  = (const float*)d_in[11];
    const float* fw3  = (const float*)d_in[12];
    const float* bias = (const float*)d_in[13];

    cudaFuncSetAttribute(conv_kernel, cudaFuncAttributeMaxDynamicSharedMemorySize,
                         CONV_SMEM);
    cudaFuncSetAttribute(mix_kernel, cudaFuncAttributeMaxDynamicSharedMemorySize,
                         MIX_SMEM_TOTAL);

    weights_kernel<<<13, 128>>>(sp, sph, bw1, bb1, bw2, bb2, bw3,
                                fw1, fb1, fw2, fb2, fw3);
    uprep_kernel<<<19, 128>>>();

    dim3 gA(64, CH, 2);
    conv_kernel<<<gA, 256, CONV_SMEM>>>(x);

    mix_kernel<<<4096 / MIX_TILES, 128, MIX_SMEM_TOTAL>>>(bias, (float*)d_out);
}

// round 16
// speedup vs baseline: 1.2624x; 1.1933x over previous
#include <cuda_runtime.h>
#include <cuda_bf16.h>
#include <math.h>
#include <stdint.h>

#define NVEC 12
#define CIN  8
#define COUT 8
#define DIM  64
#define VOX  (DIM*DIM*DIM)      // 262144
#define CH   (CIN*NVEC)         // 96

__device__ float g_sw[CH * 125];            // taps [c][kx*25+ky*5+kz]
__device__ float g_U[CH * 25 * 8];          // Winograd taps [c][kx*5+ky][8]
__device__ float g_fwm[CH * CH];            // mixing matrix [oc][fv]
__device__ float g_y[(size_t)2 * CH * VOX]; // conv output scratch

__device__ __forceinline__ float gelu_exact(float v) {
    return 0.5f * v * (1.0f + erff(v * 0.70710678118654752440f));
}

// ---------------------------------------------------------------------------
// Kernel W: tiny MLPs -> g_sw taps + g_fwm. MLP weights staged in smem.
// ---------------------------------------------------------------------------
__global__ __launch_bounds__(128) void weights_kernel(
    const float* __restrict__ sp, const float* __restrict__ sph,
    const float* __restrict__ bw1, const float* __restrict__ bb1,
    const float* __restrict__ bw2, const float* __restrict__ bb2,
    const float* __restrict__ bw3,
    const float* __restrict__ fw1, const float* __restrict__ fb1,
    const float* __restrict__ fw2, const float* __restrict__ fb2,
    const float* __restrict__ fw3)
{
    __shared__ float swm[872];
    int lt = threadIdx.x;
    for (int i = lt; i < 112; i += 128) swm[i] = bw1[i];
    if (lt < 8)  swm[112 + lt] = bb1[lt];
    for (int i = lt; i < 64;  i += 128) swm[120 + i] = bw2[i];
    if (lt < 8)  swm[184 + lt] = bb2[lt];
    for (int i = lt; i < 64;  i += 128) swm[192 + i] = bw3[i];
    if (lt < 24) swm[256 + lt] = fw1[lt];
    if (lt < 8)  swm[280 + lt] = fb1[lt];
    for (int i = lt; i < 64;  i += 128) swm[288 + i] = fw2[i];
    if (lt < 8)  swm[352 + lt] = fb2[lt];
    for (int i = lt; i < 512; i += 128) swm[360 + i] = fw3[i];
    __syncthreads();
    const float *s_bw1 = swm, *s_bb1 = swm+112, *s_bw2 = swm+120, *s_bb2 = swm+184,
                *s_bw3 = swm+192, *s_fw1 = swm+256, *s_fb1 = swm+280,
                *s_fw2 = swm+288, *s_fb2 = swm+352, *s_fw3 = swm+360;

    int tid = blockIdx.x * blockDim.x + threadIdx.x;
    if (tid < 1500) {
        int r = tid;
        float s0 = sp[2 * r], s1 = sp[2 * r + 1];
        float a[14];
        a[0] = s0; a[1] = s1;
        a[2] = s0 * s0; a[3] = s0 * s1; a[4] = s1 * s0; a[5] = s1 * s1;
        #pragma unroll
        for (int i = 0; i < 4; i++) { a[6 + 2*i] = a[2 + i] * s0; a[7 + 2*i] = a[2 + i] * s1; }
        float h1[8], h2[8];
        #pragma unroll
        for (int j = 0; j < 8; j++) {
            float s = s_bb1[j];
            #pragma unroll
            for (int i = 0; i < 14; i++) s += s_bw1[j * 14 + i] * a[i];
            h1[j] = gelu_exact(s);
        }
        #pragma unroll
        for (int j = 0; j < 8; j++) {
            float s = s_bb2[j];
            #pragma unroll
            for (int i = 0; i < 8; i++) s += s_bw2[j * 8 + i] * h1[i];
            h2[j] = gelu_exact(s);
        }
        int k = r / 12, v = r % 12;
        #pragma unroll
        for (int f = 0; f < 8; f++) {
            float o = 0.f;
            #pragma unroll
            for (int i = 0; i < 8; i++) o += s_bw3[f * 8 + i] * h2[i];
            g_sw[(f * 12 + v) * 125 + k] = o;
        }
    } else if (tid < 1644) {
        int r = tid - 1500;
        float c0 = sph[r];
        float a0 = c0, a1 = c0 * c0, a2 = c0 * c0 * c0;
        float h1[8], h2[8];
        #pragma unroll
        for (int j = 0; j < 8; j++) {
            float s = s_fb1[j] + s_fw1[j*3+0]*a0 + s_fw1[j*3+1]*a1 + s_fw1[j*3+2]*a2;
            h1[j] = gelu_exact(s);
        }
        #pragma unroll
        for (int j = 0; j < 8; j++) {
            float s = s_fb2[j];
            #pragma unroll
            for (int i = 0; i < 8; i++) s += s_fw2[j * 8 + i] * h1[i];
            h2[j] = gelu_exact(s);
        }
        int v = r / 12, w = r % 12;
        #pragma unroll
        for (int col = 0; col < 64; col++) {
            float o = 0.f;
            #pragma unroll
            for (int i = 0; i < 8; i++) o += s_fw3[col * 8 + i] * h2[i];
            int f = col >> 3, g = col & 7;
            g_fwm[(g * 12 + w) * CH + (f * 12 + v)] = o;
        }
    }
}

// ---------------------------------------------------------------------------
// Kernel U: Winograd F(4,5) tap transform U = G*t.
// ---------------------------------------------------------------------------
__global__ __launch_bounds__(128) void uprep_kernel()
{
    int tid = blockIdx.x * blockDim.x + threadIdx.x;
    if (tid >= CH * 25) return;
    int c = tid / 25, kxky = tid % 25;
    const float* tp = &g_sw[c * 125 + kxky * 5];
    float t0 = tp[0], t1 = tp[1], t2 = tp[2], t3 = tp[3], t4 = tp[4];
    float* up = &g_U[(c * 25 + kxky) * 8];
    up[0] = -t0;
    up[1] = (-2.f/9.f) * (t0 + t1 + t2 + t3 + t4);
    up[2] = (-2.f/9.f) * (t0 - t1 + t2 - t3 + t4);
    up[3] = (1.f/90.f) * (t0 + 2.f*t1 + 4.f*t2 + 8.f*t3 + 16.f*t4);
    up[4] = (1.f/90.f) * (t0 - 2.f*t1 + 4.f*t2 - 8.f*t3 + 16.f*t4);
    up[5] = (1.f/45.f) * (32.f*t0 + 16.f*t1 + 8.f*t2 + 4.f*t3 + 2.f*t4);
    up[6] = (1.f/45.f) * (32.f*t0 - 16.f*t1 + 8.f*t2 - 4.f*t3 + 2.f*t4);
    up[7] = t4;
}

// ---------------------------------------------------------------------------
// Kernel A: depthwise 5x5x5 conv via Winograd F(4,5) along z.
// Tile 16x8x32, 256 threads, 4 x-columns per thread.
// Phase 1 restructured as explicit batch-of-8 LDG->STS pipeline (MLP >= 8).
// ---------------------------------------------------------------------------
#define CSX   0
#define CSVLO 8640                 // s_x = 20*12*36
#define CSVHI 17280                // + 240*36
#define CSU   25920                // + 240*36
#define CONV_SMEM ((25920 + 200) * 4)

__global__ __launch_bounds__(256, 2) void conv_kernel(const float* __restrict__ x)
{
    extern __shared__ __align__(16) float cs[];
    float* s_x   = cs + CSX;     // 20 x 12 x 36
    float* s_vlo = cs + CSVLO;   // 240 icols x 36
    float* s_vhi = cs + CSVHI;
    float* s_u   = cs + CSU;     // 200

    int tile = blockIdx.x;            // 0..63
    int c    = blockIdx.y;            // 0..95
    int b    = blockIdx.z;
    int tx = tile >> 4, ty = (tile >> 1) & 7, tz = tile & 1;   // tx 0..3
    int t = threadIdx.x;

    for (int i = t; i < 200; i += 256) s_u[i] = g_U[c * 200 + i];

    // ---- phase 1: halo 20 x 12 x 36, batch-of-8 pipelined loads ----
    const float* xb = x + (size_t)(b * CH + c) * VOX;
    int gx0 = tx * 16 - 2, gy0 = ty * 8 - 2, gz0 = tz * 32 - 2;
    #pragma unroll
    for (int base = 0; base < 8640; base += 2048) {
        float vv[8];
        #pragma unroll
        for (int j = 0; j < 8; j++) {
            int i = base + j * 256 + t;
            vv[j] = 0.f;
            if (i < 8640) {
                int lx = i / 432, r = i % 432, ly = r / 36, lz = r % 36;
                int gx = gx0 + lx, gy = gy0 + ly, gz = gz0 + lz;
                if ((unsigned)gx < 64u && (unsigned)gy < 64u && (unsigned)gz < 64u)
                    vv[j] = xb[(gx << 12) + (gy << 6) + gz];
            }
        }
        #pragma unroll
        for (int j = 0; j < 8; j++) {
            int i = base + j * 256 + t;
            if (i < 8640) s_x[i] = vv[j];
        }
    }
    __syncthreads();

    // ---- phase 2: V = BT*d, 240 cols x 8 windows ----
    for (int i = t; i < 1920; i += 256) {
        int win  = i / 240;
        int icol = i - win * 240;
        const float4* dp = (const float4*)&s_x[icol * 36 + win * 4];
        float4 da = dp[0], db = dp[1];
        float d0 = da.x, d1 = da.y, d2 = da.z, d3 = da.w;
        float d4 = db.x, d5 = db.y, d6 = db.z, d7 = db.w;
        float V0 = (d6 - d0) + 5.25f * (d2 - d4);
        float V7 = (d7 - d1) + 5.25f * (d3 - d5);
        float P = fmaf(-4.25f, d4, d2) + d6;
        float Q = fmaf(-4.25f, d3, d1) + d5;
        float R = fmaf(0.25f, d2, fmaf(-1.25f, d4, d6));
        float S = fmaf(0.5f, d1, fmaf(-2.5f, d3, 2.f * d5));
        float T = fmaf(4.f, d2, fmaf(-5.f, d4, d6));
        float W = fmaf(2.f, d1, fmaf(-2.5f, d3, 0.5f * d5));
        *(float4*)&s_vlo[icol * 36 + win * 4] = make_float4(V0, P + Q, P - Q, R + S);
        *(float4*)&s_vhi[icol * 36 + win * 4] = make_float4(R - S, T + W, T - W, V7);
    }
    __syncthreads();

    // ---- phase 3: 4 x-columns per thread ----
    int xq = t >> 6;           // 0..3
    int oy = (t >> 3) & 7;
    int w  = t & 7;            // z-window
    int x0 = 4 * xq;

    float acc[4][8];
    #pragma unroll
    for (int cc = 0; cc < 4; cc++)
        #pragma unroll
        for (int i = 0; i < 8; i++) acc[cc][i] = 0.f;

    #pragma unroll
    for (int ky = 0; ky < 5; ky++) {
        float U[5][8];
        #pragma unroll
        for (int j = 0; j < 5; j++) {
            const float4* us = (const float4*)&s_u[(j * 5 + ky) * 8];
            float4 ua = us[0], ub = us[1];
            U[j][0] = ua.x; U[j][1] = ua.y; U[j][2] = ua.z; U[j][3] = ua.w;
            U[j][4] = ub.x; U[j][5] = ub.y; U[j][6] = ub.z; U[j][7] = ub.w;
        }
        #pragma unroll
        for (int d = 0; d < 8; d++) {
            int icol = (x0 + d) * 12 + oy + ky;
            float4 vl = *(const float4*)&s_vlo[icol * 36 + w * 4];
            float4 vh = *(const float4*)&s_vhi[icol * 36 + w * 4];
            float V[8] = { vl.x, vl.y, vl.z, vl.w, vh.x, vh.y, vh.z, vh.w };
            #pragma unroll
            for (int cc = 0; cc < 4; cc++) {
                int j = d - cc;
                if (j >= 0 && j <= 4) {
                    #pragma unroll
                    for (int i = 0; i < 8; i++) acc[cc][i] += U[j][i] * V[i];
                }
            }
        }
    }

    size_t base = (size_t)(b * CH + c) * VOX;
    int gz = tz * 32 + w * 4;
    int gy = ty * 8 + oy;
    #pragma unroll
    for (int cc = 0; cc < 4; cc++) {
        float* m = acc[cc];
        int gx = tx * 16 + x0 + cc;
        float e1 = m[1] + m[2], f1 = m[1] - m[2];
        float e2 = m[3] + m[4], f2 = m[3] - m[4];
        float e3 = m[5] + m[6], f3 = m[5] - m[6];
        float y0 = m[0] + e1 + e2 + e3;
        float y1 = fmaf(2.f, f2, f1) + 0.5f * f3;
        float y2 = fmaf(4.f, e2, e1) + 0.25f * e3;
        float y3 = fmaf(8.f, f2, f1) + fmaf(0.125f, f3, m[7]);
        *(float4*)&g_y[base + (gx << 12) + (gy << 6) + gz] =
            make_float4(y0, y1, y2, y3);
    }
}

// ---------------------------------------------------------------------------
// Kernel B: per-voxel 96x96 mixing — R13 fused-pass version (known good).
// ---------------------------------------------------------------------------
#define PA32 52
#define PB32 52
#define PD   132
#define OFF_AH 0
#define OFF_AL 26624
#define OFF_BH 53248
#define OFF_BL 73216
#define MIX_SMEM_TOTAL 93184
#define MIX_TILES 4

__device__ __forceinline__ void mma16816(float* c, const uint32_t a[4],
                                         uint32_t b0, uint32_t b1) {
    asm volatile(
        "mma.sync.aligned.m16n8k16.row.col.f32.bf16.bf16.f32 "
        "{%0,%1,%2,%3}, {%4,%5,%6,%7}, {%8,%9}, {%0,%1,%2,%3};"
        : "+f"(c[0]), "+f"(c[1]), "+f"(c[2]), "+f"(c[3])
        : "r"(a[0]), "r"(a[1]), "r"(a[2]), "r"(a[3]), "r"(b0), "r"(b1));
}

__device__ __forceinline__ void split2(float y0, float y1, uint32_t& hi, uint32_t& lo) {
    uint32_t u0 = __float_as_uint(y0), u1 = __float_as_uint(y1);
    float h0 = __uint_as_float(u0 & 0xFFFF0000u);
    float h1 = __uint_as_float(u1 & 0xFFFF0000u);
    hi = __byte_perm(u0, u1, 0x7632);
    asm("cvt.rn.bf16x2.f32 %0, %1, %2;" : "=r"(lo) : "f"(y1 - h1), "f"(y0 - h0));
}

__global__ __launch_bounds__(128) void mix_kernel(
    const float* __restrict__ bias, float* __restrict__ out)
{
    extern __shared__ __align__(16) char smem[];
    uint32_t* Ah = (uint32_t*)(smem + OFF_AH);
    uint32_t* Al = (uint32_t*)(smem + OFF_AL);
    uint32_t* Bh = (uint32_t*)(smem + OFF_BH);
    uint32_t* Bl = (uint32_t*)(smem + OFF_BL);

    int t    = threadIdx.x;
    int wid  = t >> 5;
    int lane = t & 31;
    int g    = lane >> 2;
    int q    = lane & 3;

    for (int idx = t; idx < CH * 48; idx += 128) {
        int oc = idx / 48, j = idx % 48;
        uint32_t hi, lo;
        split2(g_fwm[oc * CH + 2 * j], g_fwm[oc * CH + 2 * j + 1], hi, lo);
        Bh[oc * PB32 + j] = hi;
        Bl[oc * PB32 + j] = lo;
    }
    float bv[8];
    #pragma unroll
    for (int i = 0; i < 8; i++) bv[i] = bias[i];

    for (int it = 0; it < MIX_TILES; it++) {
        int tv = blockIdx.x * MIX_TILES + it;
        int b  = tv >> 11;
        int p0 = (tv & 2047) * 128;

        {
            const float* yb = g_y + (size_t)b * CH * VOX + p0 + t;
            int sw = (t >> 3) & 3;
            #pragma unroll 8
            for (int cp = 0; cp < 48; cp++) {
                uint32_t hi, lo;
                split2(yb[(size_t)(2 * cp) * VOX], yb[(size_t)(2 * cp + 1) * VOX], hi, lo);
                Ah[t * PA32 + (cp ^ sw)] = hi;
                Al[t * PA32 + (cp ^ sw)] = lo;
            }
        }
        __syncthreads();

        int m0 = wid * 32;
        float acc[2][12][4];
        #pragma unroll
        for (int mt = 0; mt < 2; mt++)
            #pragma unroll
            for (int n = 0; n < 12; n++)
                #pragma unroll
                for (int i = 0; i < 4; i++) acc[mt][n][i] = 0.f;

        #pragma unroll
        for (int k = 0; k < 6; k++) {
            int c0 = 8 * k + q;
            uint32_t afh[2][4], afl[2][4];
            #pragma unroll
            for (int mt = 0; mt < 2; mt++) {
                int row0 = m0 + mt * 16 + g;
                int s0 = 2 * mt, s1 = 2 * mt + 1;
                int i00 = row0 * PA32       + (c0 ^ s0);
                int i01 = (row0 + 8) * PA32 + (c0 ^ s1);
                int i10 = row0 * PA32       + ((c0 + 4) ^ s0);
                int i11 = (row0 + 8) * PA32 + ((c0 + 4) ^ s1);
                afh[mt][0] = Ah[i00]; afh[mt][1] = Ah[i01];
                afh[mt][2] = Ah[i10]; afh[mt][3] = Ah[i11];
                afl[mt][0] = Al[i00]; afl[mt][1] = Al[i01];
                afl[mt][2] = Al[i10]; afl[mt][3] = Al[i11];
            }
            #pragma unroll
            for (int n = 0; n < 12; n++) {
                const uint32_t* pbh = Bh + (n * 8 + g) * PB32 + 8 * k + q;
                const uint32_t* pbl = Bl + (n * 8 + g) * PB32 + 8 * k + q;
                uint32_t b0h = pbh[0], b1h = pbh[4];
                uint32_t b0l = pbl[0], b1l = pbl[4];
                mma16816(acc[0][n], afh[0], b0h, b1h);
                mma16816(acc[1][n], afh[1], b0h, b1h);
                mma16816(acc[0][n], afl[0], b0h, b1h);
                mma16816(acc[1][n], afl[1], b0h, b1h);
                mma16816(acc[0][n], afh[0], b0l, b1l);
                mma16816(acc[1][n], afh[1], b0l, b1l);
            }
        }

        __syncthreads();
        float* D = (float*)(smem + OFF_AH);
        #pragma unroll
        for (int mt = 0; mt < 2; mt++) {
            int r1 = m0 + mt * 16 + g;
            #pragma unroll
            for (int n = 0; n < 12; n++) {
                int ocb = n * 8 + 2 * q;
                D[(ocb)     * PD + r1]     = acc[mt][n][0];
                D[(ocb + 1) * PD + r1]     = acc[mt][n][1];
                D[(ocb)     * PD + r1 + 8] = acc[mt][n][2];
                D[(ocb + 1) * PD + r1 + 8] = acc[mt][n][3];
            }
        }
        __syncthreads();

        float* ob = out + (size_t)b * CH * VOX + p0 + t;
        #pragma unroll
        for (int c = 0; c < CH; c++)
            ob[(size_t)c * VOX] = D[c * PD + t] + bv[c / 12];
        __syncthreads();
    }
}

// ---------------------------------------------------------------------------
extern "C" void kernel_launch(void* const* d_in, const int* in_sizes, int n_in,
                              void* d_out, int out_size)
{
    const float* x    = (const float*)d_in[0];
    const float* sp   = (const float*)d_in[1];
    const float* sph  = (const float*)d_in[2];
    const float* bw1  = (const float*)d_in[3];
    const float* bb1  = (const float*)d_in[4];
    const float* bw2  = (const float*)d_in[5];
    const float* bb2  = (const float*)d_in[6];
    const float* bw3  = (const float*)d_in[7];
    const float* fw1  = (const float*)d_in[8];
    const float* fb1  = (const float*)d_in[9];
    const float* fw2  = (const float*)d_in[10];
    const float* fb2  = (const float*)d_in[11];
    const float* fw3  = (const float*)d_in[12];
    const float* bias = (const float*)d_in[13];

    cudaFuncSetAttribute(conv_kernel, cudaFuncAttributeMaxDynamicSharedMemorySize,
                         CONV_SMEM);
    cudaFuncSetAttribute(mix_kernel, cudaFuncAttributeMaxDynamicSharedMemorySize,
                         MIX_SMEM_TOTAL);

    weights_kernel<<<13, 128>>>(sp, sph, bw1, bb1, bw2, bb2, bw3,
                                fw1, fb1, fw2, fb2, fw3);
    uprep_kernel<<<19, 128>>>();

    dim3 gA(64, CH, 2);
    conv_kernel<<<gA, 256, CONV_SMEM>>>(x);

    mix_kernel<<<4096 / MIX_TILES, 128, MIX_SMEM_TOTAL>>>(bias, (float*)d_out);
}

// round 17
// speedup vs baseline: 1.3709x; 1.0860x over previous
#include <cuda_runtime.h>
#include <cuda_bf16.h>
#include <math.h>
#include <stdint.h>

#define NVEC 12
#define CIN  8
#define COUT 8
#define DIM  64
#define VOX  (DIM*DIM*DIM)      // 262144
#define CH   (CIN*NVEC)         // 96

__device__ float g_sw[CH * 125];            // taps [c][kx*25+ky*5+kz]
__device__ float g_U[CH * 25 * 8];          // Winograd taps [c][kx*5+ky][8]
__device__ float g_fwm[CH * CH];            // mixing matrix [oc][fv]
__device__ float g_y[(size_t)2 * CH * VOX]; // conv output scratch

__device__ __forceinline__ float gelu_exact(float v) {
    return 0.5f * v * (1.0f + erff(v * 0.70710678118654752440f));
}

// ---------------------------------------------------------------------------
// Kernel W: tiny MLPs -> g_sw taps + g_fwm. MLP weights staged in smem.
// ---------------------------------------------------------------------------
__global__ __launch_bounds__(128) void weights_kernel(
    const float* __restrict__ sp, const float* __restrict__ sph,
    const float* __restrict__ bw1, const float* __restrict__ bb1,
    const float* __restrict__ bw2, const float* __restrict__ bb2,
    const float* __restrict__ bw3,
    const float* __restrict__ fw1, const float* __restrict__ fb1,
    const float* __restrict__ fw2, const float* __restrict__ fb2,
    const float* __restrict__ fw3)
{
    __shared__ float swm[872];
    int lt = threadIdx.x;
    for (int i = lt; i < 112; i += 128) swm[i] = bw1[i];
    if (lt < 8)  swm[112 + lt] = bb1[lt];
    for (int i = lt; i < 64;  i += 128) swm[120 + i] = bw2[i];
    if (lt < 8)  swm[184 + lt] = bb2[lt];
    for (int i = lt; i < 64;  i += 128) swm[192 + i] = bw3[i];
    if (lt < 24) swm[256 + lt] = fw1[lt];
    if (lt < 8)  swm[280 + lt] = fb1[lt];
    for (int i = lt; i < 64;  i += 128) swm[288 + i] = fw2[i];
    if (lt < 8)  swm[352 + lt] = fb2[lt];
    for (int i = lt; i < 512; i += 128) swm[360 + i] = fw3[i];
    __syncthreads();
    const float *s_bw1 = swm, *s_bb1 = swm+112, *s_bw2 = swm+120, *s_bb2 = swm+184,
                *s_bw3 = swm+192, *s_fw1 = swm+256, *s_fb1 = swm+280,
                *s_fw2 = swm+288, *s_fb2 = swm+352, *s_fw3 = swm+360;

    int tid = blockIdx.x * blockDim.x + threadIdx.x;
    if (tid < 1500) {
        int r = tid;
        float s0 = sp[2 * r], s1 = sp[2 * r + 1];
        float a[14];
        a[0] = s0; a[1] = s1;
        a[2] = s0 * s0; a[3] = s0 * s1; a[4] = s1 * s0; a[5] = s1 * s1;
        #pragma unroll
        for (int i = 0; i < 4; i++) { a[6 + 2*i] = a[2 + i] * s0; a[7 + 2*i] = a[2 + i] * s1; }
        float h1[8], h2[8];
        #pragma unroll
        for (int j = 0; j < 8; j++) {
            float s = s_bb1[j];
            #pragma unroll
            for (int i = 0; i < 14; i++) s += s_bw1[j * 14 + i] * a[i];
            h1[j] = gelu_exact(s);
        }
        #pragma unroll
        for (int j = 0; j < 8; j++) {
            float s = s_bb2[j];
            #pragma unroll
            for (int i = 0; i < 8; i++) s += s_bw2[j * 8 + i] * h1[i];
            h2[j] = gelu_exact(s);
        }
        int k = r / 12, v = r % 12;
        #pragma unroll
        for (int f = 0; f < 8; f++) {
            float o = 0.f;
            #pragma unroll
            for (int i = 0; i < 8; i++) o += s_bw3[f * 8 + i] * h2[i];
            g_sw[(f * 12 + v) * 125 + k] = o;
        }
    } else if (tid < 1644) {
        int r = tid - 1500;
        float c0 = sph[r];
        float a0 = c0, a1 = c0 * c0, a2 = c0 * c0 * c0;
        float h1[8], h2[8];
        #pragma unroll
        for (int j = 0; j < 8; j++) {
            float s = s_fb1[j] + s_fw1[j*3+0]*a0 + s_fw1[j*3+1]*a1 + s_fw1[j*3+2]*a2;
            h1[j] = gelu_exact(s);
        }
        #pragma unroll
        for (int j = 0; j < 8; j++) {
            float s = s_fb2[j];
            #pragma unroll
            for (int i = 0; i < 8; i++) s += s_fw2[j * 8 + i] * h1[i];
            h2[j] = gelu_exact(s);
        }
        int v = r / 12, w = r % 12;
        #pragma unroll
        for (int col = 0; col < 64; col++) {
            float o = 0.f;
            #pragma unroll
            for (int i = 0; i < 8; i++) o += s_fw3[col * 8 + i] * h2[i];
            int f = col >> 3, g = col & 7;
            g_fwm[(g * 12 + w) * CH + (f * 12 + v)] = o;
        }
    }
}

// ---------------------------------------------------------------------------
// Kernel U: Winograd F(4,5) tap transform U = G*t.
// ---------------------------------------------------------------------------
__global__ __launch_bounds__(128) void uprep_kernel()
{
    int tid = blockIdx.x * blockDim.x + threadIdx.x;
    if (tid >= CH * 25) return;
    int c = tid / 25, kxky = tid % 25;
    const float* tp = &g_sw[c * 125 + kxky * 5];
    float t0 = tp[0], t1 = tp[1], t2 = tp[2], t3 = tp[3], t4 = tp[4];
    float* up = &g_U[(c * 25 + kxky) * 8];
    up[0] = -t0;
    up[1] = (-2.f/9.f) * (t0 + t1 + t2 + t3 + t4);
    up[2] = (-2.f/9.f) * (t0 - t1 + t2 - t3 + t4);
    up[3] = (1.f/90.f) * (t0 + 2.f*t1 + 4.f*t2 + 8.f*t3 + 16.f*t4);
    up[4] = (1.f/90.f) * (t0 - 2.f*t1 + 4.f*t2 - 8.f*t3 + 16.f*t4);
    up[5] = (1.f/45.f) * (32.f*t0 + 16.f*t1 + 8.f*t2 + 4.f*t3 + 2.f*t4);
    up[6] = (1.f/45.f) * (32.f*t0 - 16.f*t1 + 8.f*t2 - 4.f*t3 + 2.f*t4);
    up[7] = t4;
}

// ---------------------------------------------------------------------------
// Kernel A: depthwise 5x5x5 conv via Winograd F(4,5) along z.
// Tile 16x8x32, 256 threads, 4 x-columns per thread.
// Phase 1: ONE mega-batch of 34 in-flight LDGs per thread (MLP ~34).
// ---------------------------------------------------------------------------
#define CSX   0
#define CSVLO 8640                 // s_x = 20*12*36
#define CSVHI 17280                // + 240*36
#define CSU   25920                // + 240*36
#define CONV_SMEM ((25920 + 200) * 4)

__global__ __launch_bounds__(256, 2) void conv_kernel(const float* __restrict__ x)
{
    extern __shared__ __align__(16) float cs[];
    float* s_x   = cs + CSX;     // 20 x 12 x 36
    float* s_vlo = cs + CSVLO;   // 240 icols x 36
    float* s_vhi = cs + CSVHI;
    float* s_u   = cs + CSU;     // 200

    int tile = blockIdx.x;            // 0..63
    int c    = blockIdx.y;            // 0..95
    int b    = blockIdx.z;
    int tx = tile >> 4, ty = (tile >> 1) & 7, tz = tile & 1;   // tx 0..3
    int t = threadIdx.x;

    for (int i = t; i < 200; i += 256) s_u[i] = g_U[c * 200 + i];

    // ---- phase 1: halo 20 x 12 x 36, single batch of 34 pipelined loads ----
    const float* xb = x + (size_t)(b * CH + c) * VOX;
    int gx0 = tx * 16 - 2, gy0 = ty * 8 - 2, gz0 = tz * 32 - 2;
    {
        float vv[34];
        #pragma unroll
        for (int j = 0; j < 34; j++) {
            int i = j * 256 + t;
            vv[j] = 0.f;
            if (i < 8640) {
                int lx = i / 432, r = i % 432, ly = r / 36, lz = r % 36;
                int gx = gx0 + lx, gy = gy0 + ly, gz = gz0 + lz;
                if ((unsigned)gx < 64u && (unsigned)gy < 64u && (unsigned)gz < 64u)
                    vv[j] = xb[(gx << 12) + (gy << 6) + gz];
            }
        }
        #pragma unroll
        for (int j = 0; j < 34; j++) {
            int i = j * 256 + t;
            if (i < 8640) s_x[i] = vv[j];
        }
    }
    __syncthreads();

    // ---- phase 2: V = BT*d, 240 cols x 8 windows ----
    for (int i = t; i < 1920; i += 256) {
        int win  = i / 240;
        int icol = i - win * 240;
        const float4* dp = (const float4*)&s_x[icol * 36 + win * 4];
        float4 da = dp[0], db = dp[1];
        float d0 = da.x, d1 = da.y, d2 = da.z, d3 = da.w;
        float d4 = db.x, d5 = db.y, d6 = db.z, d7 = db.w;
        float V0 = (d6 - d0) + 5.25f * (d2 - d4);
        float V7 = (d7 - d1) + 5.25f * (d3 - d5);
        float P = fmaf(-4.25f, d4, d2) + d6;
        float Q = fmaf(-4.25f, d3, d1) + d5;
        float R = fmaf(0.25f, d2, fmaf(-1.25f, d4, d6));
        float S = fmaf(0.5f, d1, fmaf(-2.5f, d3, 2.f * d5));
        float T = fmaf(4.f, d2, fmaf(-5.f, d4, d6));
        float W = fmaf(2.f, d1, fmaf(-2.5f, d3, 0.5f * d5));
        *(float4*)&s_vlo[icol * 36 + win * 4] = make_float4(V0, P + Q, P - Q, R + S);
        *(float4*)&s_vhi[icol * 36 + win * 4] = make_float4(R - S, T + W, T - W, V7);
    }
    __syncthreads();

    // ---- phase 3: 4 x-columns per thread ----
    int xq = t >> 6;           // 0..3
    int oy = (t >> 3) & 7;
    int w  = t & 7;            // z-window
    int x0 = 4 * xq;

    float acc[4][8];
    #pragma unroll
    for (int cc = 0; cc < 4; cc++)
        #pragma unroll
        for (int i = 0; i < 8; i++) acc[cc][i] = 0.f;

    #pragma unroll
    for (int ky = 0; ky < 5; ky++) {
        float U[5][8];
        #pragma unroll
        for (int j = 0; j < 5; j++) {
            const float4* us = (const float4*)&s_u[(j * 5 + ky) * 8];
            float4 ua = us[0], ub = us[1];
            U[j][0] = ua.x; U[j][1] = ua.y; U[j][2] = ua.z; U[j][3] = ua.w;
            U[j][4] = ub.x; U[j][5] = ub.y; U[j][6] = ub.z; U[j][7] = ub.w;
        }
        #pragma unroll
        for (int d = 0; d < 8; d++) {
            int icol = (x0 + d) * 12 + oy + ky;
            float4 vl = *(const float4*)&s_vlo[icol * 36 + w * 4];
            float4 vh = *(const float4*)&s_vhi[icol * 36 + w * 4];
            float V[8] = { vl.x, vl.y, vl.z, vl.w, vh.x, vh.y, vh.z, vh.w };
            #pragma unroll
            for (int cc = 0; cc < 4; cc++) {
                int j = d - cc;
                if (j >= 0 && j <= 4) {
                    #pragma unroll
                    for (int i = 0; i < 8; i++) acc[cc][i] += U[j][i] * V[i];
                }
            }
        }
    }

    size_t base = (size_t)(b * CH + c) * VOX;
    int gz = tz * 32 + w * 4;
    int gy = ty * 8 + oy;
    #pragma unroll
    for (int cc = 0; cc < 4; cc++) {
        float* m = acc[cc];
        int gx = tx * 16 + x0 + cc;
        float e1 = m[1] + m[2], f1 = m[1] - m[2];
        float e2 = m[3] + m[4], f2 = m[3] - m[4];
        float e3 = m[5] + m[6], f3 = m[5] - m[6];
        float y0 = m[0] + e1 + e2 + e3;
        float y1 = fmaf(2.f, f2, f1) + 0.5f * f3;
        float y2 = fmaf(4.f, e2, e1) + 0.25f * e3;
        float y3 = fmaf(8.f, f2, f1) + fmaf(0.125f, f3, m[7]);
        *(float4*)&g_y[base + (gx << 12) + (gy << 6) + gz] =
            make_float4(y0, y1, y2, y3);
    }
}

// ---------------------------------------------------------------------------
// Kernel B: per-voxel 96x96 mixing — R13 fused-pass + batched A-staging loads.
// ---------------------------------------------------------------------------
#define PA32 52
#define PB32 52
#define PD   132
#define OFF_AH 0
#define OFF_AL 26624
#define OFF_BH 53248
#define OFF_BL 73216
#define MIX_SMEM_TOTAL 93184
#define MIX_TILES 4

__device__ __forceinline__ void mma16816(float* c, const uint32_t a[4],
                                         uint32_t b0, uint32_t b1) {
    asm volatile(
        "mma.sync.aligned.m16n8k16.row.col.f32.bf16.bf16.f32 "
        "{%0,%1,%2,%3}, {%4,%5,%6,%7}, {%8,%9}, {%0,%1,%2,%3};"
        : "+f"(c[0]), "+f"(c[1]), "+f"(c[2]), "+f"(c[3])
        : "r"(a[0]), "r"(a[1]), "r"(a[2]), "r"(a[3]), "r"(b0), "r"(b1));
}

__device__ __forceinline__ void split2(float y0, float y1, uint32_t& hi, uint32_t& lo) {
    uint32_t u0 = __float_as_uint(y0), u1 = __float_as_uint(y1);
    float h0 = __uint_as_float(u0 & 0xFFFF0000u);
    float h1 = __uint_as_float(u1 & 0xFFFF0000u);
    hi = __byte_perm(u0, u1, 0x7632);
    asm("cvt.rn.bf16x2.f32 %0, %1, %2;" : "=r"(lo) : "f"(y1 - h1), "f"(y0 - h0));
}

__global__ __launch_bounds__(128) void mix_kernel(
    const float* __restrict__ bias, float* __restrict__ out)
{
    extern __shared__ __align__(16) char smem[];
    uint32_t* Ah = (uint32_t*)(smem + OFF_AH);
    uint32_t* Al = (uint32_t*)(smem + OFF_AL);
    uint32_t* Bh = (uint32_t*)(smem + OFF_BH);
    uint32_t* Bl = (uint32_t*)(smem + OFF_BL);

    int t    = threadIdx.x;
    int wid  = t >> 5;
    int lane = t & 31;
    int g    = lane >> 2;
    int q    = lane & 3;

    for (int idx = t; idx < CH * 48; idx += 128) {
        int oc = idx / 48, j = idx % 48;
        uint32_t hi, lo;
        split2(g_fwm[oc * CH + 2 * j], g_fwm[oc * CH + 2 * j + 1], hi, lo);
        Bh[oc * PB32 + j] = hi;
        Bl[oc * PB32 + j] = lo;
    }
    float bv[8];
    #pragma unroll
    for (int i = 0; i < 8; i++) bv[i] = bias[i];

    for (int it = 0; it < MIX_TILES; it++) {
        int tv = blockIdx.x * MIX_TILES + it;
        int b  = tv >> 11;
        int p0 = (tv & 2047) * 128;

        // ---- A staging: batches of 24 in-flight loads (12 pairs) ----
        {
            const float* yb = g_y + (size_t)b * CH * VOX + p0 + t;
            int sw = (t >> 3) & 3;
            #pragma unroll
            for (int grp = 0; grp < 48; grp += 12) {
                float y0v[12], y1v[12];
                #pragma unroll
                for (int j = 0; j < 12; j++) {
                    y0v[j] = yb[(size_t)(2 * (grp + j)) * VOX];
                    y1v[j] = yb[(size_t)(2 * (grp + j) + 1) * VOX];
                }
                #pragma unroll
                for (int j = 0; j < 12; j++) {
                    uint32_t hi, lo;
                    split2(y0v[j], y1v[j], hi, lo);
                    int cp = grp + j;
                    Ah[t * PA32 + (cp ^ sw)] = hi;
                    Al[t * PA32 + (cp ^ sw)] = lo;
                }
            }
        }
        __syncthreads();

        int m0 = wid * 32;
        float acc[2][12][4];
        #pragma unroll
        for (int mt = 0; mt < 2; mt++)
            #pragma unroll
            for (int n = 0; n < 12; n++)
                #pragma unroll
                for (int i = 0; i < 4; i++) acc[mt][n][i] = 0.f;

        #pragma unroll
        for (int k = 0; k < 6; k++) {
            int c0 = 8 * k + q;
            uint32_t afh[2][4], afl[2][4];
            #pragma unroll
            for (int mt = 0; mt < 2; mt++) {
                int row0 = m0 + mt * 16 + g;
                int s0 = 2 * mt, s1 = 2 * mt + 1;
                int i00 = row0 * PA32       + (c0 ^ s0);
                int i01 = (row0 + 8) * PA32 + (c0 ^ s1);
                int i10 = row0 * PA32       + ((c0 + 4) ^ s0);
                int i11 = (row0 + 8) * PA32 + ((c0 + 4) ^ s1);
                afh[mt][0] = Ah[i00]; afh[mt][1] = Ah[i01];
                afh[mt][2] = Ah[i10]; afh[mt][3] = Ah[i11];
                afl[mt][0] = Al[i00]; afl[mt][1] = Al[i01];
                afl[mt][2] = Al[i10]; afl[mt][3] = Al[i11];
            }
            #pragma unroll
            for (int n = 0; n < 12; n++) {
                const uint32_t* pbh = Bh + (n * 8 + g) * PB32 + 8 * k + q;
                const uint32_t* pbl = Bl + (n * 8 + g) * PB32 + 8 * k + q;
                uint32_t b0h = pbh[0], b1h = pbh[4];
                uint32_t b0l = pbl[0], b1l = pbl[4];
                mma16816(acc[0][n], afh[0], b0h, b1h);
                mma16816(acc[1][n], afh[1], b0h, b1h);
                mma16816(acc[0][n], afl[0], b0h, b1h);
                mma16816(acc[1][n], afl[1], b0h, b1h);
                mma16816(acc[0][n], afh[0], b0l, b1l);
                mma16816(acc[1][n], afh[1], b0l, b1l);
            }
        }

        __syncthreads();
        float* D = (float*)(smem + OFF_AH);
        #pragma unroll
        for (int mt = 0; mt < 2; mt++) {
            int r1 = m0 + mt * 16 + g;
            #pragma unroll
            for (int n = 0; n < 12; n++) {
                int ocb = n * 8 + 2 * q;
                D[(ocb)     * PD + r1]     = acc[mt][n][0];
                D[(ocb + 1) * PD + r1]     = acc[mt][n][1];
                D[(ocb)     * PD + r1 + 8] = acc[mt][n][2];
                D[(ocb + 1) * PD + r1 + 8] = acc[mt][n][3];
            }
        }
        __syncthreads();

        float* ob = out + (size_t)b * CH * VOX + p0 + t;
        #pragma unroll
        for (int c = 0; c < CH; c++)
            ob[(size_t)c * VOX] = D[c * PD + t] + bv[c / 12];
        __syncthreads();
    }
}

// ---------------------------------------------------------------------------
extern "C" void kernel_launch(void* const* d_in, const int* in_sizes, int n_in,
                              void* d_out, int out_size)
{
    const float* x    = (const float*)d_in[0];
    const float* sp   = (const float*)d_in[1];
    const float* sph  = (const float*)d_in[2];
    const float* bw1  = (const float*)d_in[3];
    const float* bb1  = (const float*)d_in[4];
    const float* bw2  = (const float*)d_in[5];
    const float* bb2  = (const float*)d_in[6];
    const float* bw3  = (const float*)d_in[7];
    const float* fw1  = (const float*)d_in[8];
    const float* fb1  = (const float*)d_in[9];
    const float* fw2  = (const float*)d_in[10];
    const float* fb2  = (const float*)d_in[11];
    const float* fw3  = (const float*)d_in[12];
    const float* bias = (const float*)d_in[13];

    cudaFuncSetAttribute(conv_kernel, cudaFuncAttributeMaxDynamicSharedMemorySize,
                         CONV_SMEM);
    cudaFuncSetAttribute(mix_kernel, cudaFuncAttributeMaxDynamicSharedMemorySize,
                         MIX_SMEM_TOTAL);

    weights_kernel<<<13, 128>>>(sp, sph, bw1, bb1, bw2, bb2, bw3,
                                fw1, fb1, fw2, fb2, fw3);
    uprep_kernel<<<19, 128>>>();

    dim3 gA(64, CH, 2);
    conv_kernel<<<gA, 256, CONV_SMEM>>>(x);

    mix_kernel<<<4096 / MIX_TILES, 128, MIX_SMEM_TOTAL>>>(bias, (float*)d_out);
}